// round 2
// baseline (speedup 1.0000x reference)
#include <cuda_runtime.h>
#include <math.h>

#define B_  16
#define NA  512
#define LA  1024
#define CD  128
#define GD  64
#define NH  4
#define LT  128
#define ALPHA 0.2f
#define NEGV  -9000000000000000.0f

// ---------------- scratch (static device globals; no allocations) -------------
__device__ float g_av[B_*NA*CD];
__device__ float g_Wh[NH*B_*NA*GD];
__device__ float g_src[NH*B_*NA];
__device__ float g_dst[NH*B_*NA];
__device__ float g_multi[B_*NA*NH*GD];
__device__ float g_Wh2[B_*NA*CD];
__device__ float g_src2[B_*NA];
__device__ float g_dst2[B_*NA];
__device__ float g_x[B_*NA*CD];
__device__ float g_atoms_vec[B_*NA*LT];
__device__ float g_a_v[B_*NA*LT];
__device__ float g_pv0[B_*LA*CD];
__device__ float g_pv1[B_*LA*CD];
__device__ float g_pvatt[B_*LA*LT];
__device__ float g_comp[B_*LT];
__device__ float g_prot[B_*LT];

// ---------------- embedding gather -------------------------------------------
__global__ void gather_embed(const int* __restrict__ idx, const float* __restrict__ E,
                             float* __restrict__ out, int dim) {
    int i = blockIdx.x;
    int e = idx[i];
    for (int c = threadIdx.x; c < dim; c += blockDim.x)
        out[(size_t)i*dim + c] = E[(size_t)e*dim + c];
}

// ---------------- generic tiled SGEMM: C = epi(A @ B(^T)) ---------------------
// BM=BN=64, BK=16, 256 threads, 4x4 microtile.
// EPI: 0 = none, 1 = bias + leaky_relu
template<bool BT, int EPI>
__global__ void sgemm64(const float* __restrict__ A, const float* __restrict__ Bm,
                        const float* __restrict__ bias, float* __restrict__ C,
                        int M, int N, int K,
                        size_t aBat, int aMod, size_t bBat, int bDiv, size_t cBat) {
    __shared__ __align__(16) float As[16][64];
    __shared__ __align__(16) float Bs[16][64];
    int z = blockIdx.z;
    A  += (size_t)(aMod ? (z % aMod) : z) * aBat;
    Bm += (size_t)(bDiv ? (z / bDiv) : z) * bBat;
    C  += (size_t)z * cBat;
    int bn = blockIdx.x * 64, bm = blockIdx.y * 64;
    int tid = threadIdx.x;
    int tx = tid & 15, ty = tid >> 4;
    float acc[4][4] = {};
    for (int k0 = 0; k0 < K; k0 += 16) {
        for (int e = tid; e < 64*16; e += 256) {
            int m = e >> 4, k = e & 15;
            As[k][m] = A[(size_t)(bm + m) * K + k0 + k];
        }
        if (!BT) {
            for (int e = tid; e < 16*64; e += 256) {
                int k = e >> 6, n = e & 63;
                Bs[k][n] = Bm[(size_t)(k0 + k) * N + bn + n];
            }
        } else {
            for (int e = tid; e < 64*16; e += 256) {
                int n = e >> 4, k = e & 15;
                Bs[k][n] = Bm[(size_t)(bn + n) * K + k0 + k];
            }
        }
        __syncthreads();
        #pragma unroll
        for (int k = 0; k < 16; k++) {
            float4 a4 = *(const float4*)&As[k][ty*4];
            float4 b4 = *(const float4*)&Bs[k][tx*4];
            float av[4] = {a4.x, a4.y, a4.z, a4.w};
            float bv[4] = {b4.x, b4.y, b4.z, b4.w};
            #pragma unroll
            for (int i = 0; i < 4; i++)
                #pragma unroll
                for (int j = 0; j < 4; j++)
                    acc[i][j] += av[i] * bv[j];
        }
        __syncthreads();
    }
    #pragma unroll
    for (int i = 0; i < 4; i++) {
        int m = bm + ty*4 + i;
        #pragma unroll
        for (int j = 0; j < 4; j++) {
            int n = bn + tx*4 + j;
            float v = acc[i][j];
            if (EPI == 1) {
                v += bias[n];
                v = (v >= 0.f) ? v : ALPHA * v;
            }
            C[(size_t)m * N + n] = v;
        }
    }
}

// ---------------- src/dst attention dot products ------------------------------
template<int F>
__global__ void srcdst_kernel(const float* __restrict__ Wh, const float* __restrict__ a,
                              float* __restrict__ src, float* __restrict__ dst,
                              int rowsPerHead, int aHeadStride) {
    int gwarp = (blockIdx.x * blockDim.x + threadIdx.x) >> 5;
    int lane = threadIdx.x & 31;
    const float* ar = a + (size_t)(gwarp / rowsPerHead) * aHeadStride;
    const float* w = Wh + (size_t)gwarp * F;
    float s = 0.f, d = 0.f;
    #pragma unroll
    for (int i = lane; i < F; i += 32) {
        float v = w[i];
        s += v * ar[i];
        d += v * ar[F + i];
    }
    #pragma unroll
    for (int o = 16; o; o >>= 1) {
        s += __shfl_xor_sync(0xffffffffu, s, o);
        d += __shfl_xor_sync(0xffffffffu, d, o);
    }
    if (lane == 0) { src[gwarp] = s; dst[gwarp] = d; }
}

// ---------------- fused GAT attention: softmax + aggregate + elu --------------
// blockIdx.x = 32-row tile, blockIdx.y = hb (head*nb + b). 256 threads.
// dyn smem: wsm[32][513] + whs[64][F]
template<int F>
__global__ void attn_kernel(const float* __restrict__ Wh, const float* __restrict__ src,
                            const float* __restrict__ dst, const int* __restrict__ adj,
                            float* __restrict__ out, int outRowStride, int nb) {
    extern __shared__ __align__(16) float sm[];
    float* wsm = sm;                 // [32][513]
    float* whs = sm + 32 * 513;      // [64][F]
    int hb = blockIdx.y;
    int b = hb % nb, h = hb / nb;
    const float* WhB = Wh + (size_t)hb * NA * F;
    const float* srcB = src + (size_t)hb * NA;
    const float* dstB = dst + (size_t)hb * NA;
    const int* adjB = adj + (size_t)b * NA * NA;
    int row0 = blockIdx.x * 32;
    int tid = threadIdx.x, lane = tid & 31, wid = tid >> 5;

    // Phase A: masked leaky-relu logits -> softmax weights (each warp: 4 rows)
    for (int rr = 0; rr < 4; rr++) {
        int r = wid * 4 + rr;
        int i = row0 + r;
        float si = srcB[i];
        float* wrow = wsm + r * 513;
        float mx = -3.4e38f;
        const int* arow = adjB + (size_t)i * NA;
        for (int j = lane; j < NA; j += 32) {
            float e;
            if (arow[j] > 0) {
                float t = si + dstB[j];
                e = (t >= 0.f) ? t : ALPHA * t;
            } else e = NEGV;
            wrow[j] = e;
            mx = fmaxf(mx, e);
        }
        #pragma unroll
        for (int o = 16; o; o >>= 1) mx = fmaxf(mx, __shfl_xor_sync(0xffffffffu, mx, o));
        float sum = 0.f;
        for (int j = lane; j < NA; j += 32) {
            float ex = expf(wrow[j] - mx);
            wrow[j] = ex;
            sum += ex;
        }
        #pragma unroll
        for (int o = 16; o; o >>= 1) sum += __shfl_xor_sync(0xffffffffu, sum, o);
        float inv = 1.f / sum;
        for (int j = lane; j < NA; j += 32) wrow[j] *= inv;
    }
    __syncthreads();

    // Phase B: out[32][F] = w[32][512] @ Wh[512][F], register-tiled.
    constexpr int TN = F / 32;   // 2 (F=64) or 4 (F=128)
    constexpr int TM = 4;
    int tx = tid & 31, ty = tid >> 5;   // 32 x 8
    float acc[TM][TN] = {};
    for (int jc = 0; jc < NA; jc += 64) {
        for (int e = tid; e < 64 * F; e += 256)
            whs[e] = WhB[(size_t)(jc + (e / F)) * F + (e % F)];
        __syncthreads();
        #pragma unroll 4
        for (int jj = 0; jj < 64; jj++) {
            float wr[TM];
            #pragma unroll
            for (int t = 0; t < TM; t++) wr[t] = wsm[(ty*TM + t) * 513 + jc + jj];
            const float* whp = whs + jj * F + tx * TN;
            float wv[TN];
            if constexpr (TN == 2) {
                float2 t2 = *(const float2*)whp; wv[0] = t2.x; wv[1] = t2.y;
            } else {
                float4 t4 = *(const float4*)whp; wv[0] = t4.x; wv[1] = t4.y; wv[2] = t4.z; wv[3] = t4.w;
            }
            #pragma unroll
            for (int t = 0; t < TM; t++)
                #pragma unroll
                for (int u = 0; u < TN; u++)
                    acc[t][u] += wr[t] * wv[u];
        }
        __syncthreads();
    }

    // Epilogue: elu, scatter into output (with per-head column offset)
    int colOff = h * F;
    #pragma unroll
    for (int t = 0; t < TM; t++) {
        int i = row0 + ty*TM + t;
        float* op = out + (size_t)b * NA * outRowStride + (size_t)i * outRowStride + colOff + tx*TN;
        #pragma unroll
        for (int u = 0; u < TN; u++) {
            float v = acc[t][u];
            v = (v > 0.f) ? v : expm1f(v);
            op[u] = v;
        }
    }
}

// ---------------- 11x11 conv, SAME pad, relu ----------------------------------
__global__ void conv11(const float* __restrict__ in, const float* __restrict__ wconv,
                       const float* __restrict__ bconv, int layer, float* __restrict__ out) {
    __shared__ float tile[42][42];
    __shared__ float ws[121];
    int b = blockIdx.z, ly0 = blockIdx.y * 32, lx0 = blockIdx.x * 32;
    int tx = threadIdx.x, ty = threadIdx.y;
    int tid = ty * 32 + tx;
    if (tid < 121) ws[tid] = wconv[layer * 121 + tid];
    const float* inb = in + (size_t)b * LA * CD;
    for (int e = tid; e < 42*42; e += 1024) {
        int sy = e / 42, sx = e % 42;
        int gy = ly0 + sy - 5, gx = lx0 + sx - 5;
        tile[sy][sx] = (gy >= 0 && gy < LA && gx >= 0 && gx < CD) ? inb[(size_t)gy*CD + gx] : 0.f;
    }
    __syncthreads();
    float acc = bconv[layer];
    #pragma unroll
    for (int dy = 0; dy < 11; dy++)
        #pragma unroll
        for (int dx = 0; dx < 11; dx++)
            acc += tile[ty + dy][tx + dx] * ws[dy*11 + dx];
    out[(size_t)b*LA*CD + (size_t)(ly0 + ty)*CD + lx0 + tx] = fmaxf(acc, 0.f);
}

// ---------------- masked mean pool over rows ----------------------------------
__global__ void pool_kernel(const float* __restrict__ v, const float* __restrict__ mask,
                            float* __restrict__ out, int n) {
    int b = blockIdx.x, c = threadIdx.x;  // 128 threads
    const float* vb = v + (size_t)b * n * LT;
    const float* mb = mask + (size_t)b * n;
    float acc = 0.f, ms = 0.f;
    for (int i = 0; i < n; i++) {
        float m = mb[i];
        acc += vb[(size_t)i*LT + c] * m;
        ms += m;
    }
    out[b*LT + c] = acc / ms;
}

// ---------------- final head: 2x leaky_relu + dot -----------------------------
__global__ void final_kernel(const float* __restrict__ comp, const float* __restrict__ prot,
                             const float* __restrict__ pw, const float* __restrict__ pb,
                             float* __restrict__ out) {
    __shared__ float red[256];
    int b = blockIdx.x, t = threadIdx.x;
    float v = (t < 128) ? comp[b*128 + t] : prot[b*128 + t - 128];
    v = (v >= 0.f) ? v : ALPHA * v;
    v = (v >= 0.f) ? v : ALPHA * v;
    red[t] = v * pw[t];
    __syncthreads();
    for (int o = 128; o; o >>= 1) {
        if (t < o) red[t] += red[t + o];
        __syncthreads();
    }
    if (t == 0) out[b] = red[0] + pb[0];
}

// ------------------------------------------------------------------------------
extern "C" void kernel_launch(void* const* d_in, const int* in_sizes, int n_in,
                              void* d_out, int out_size) {
    const int*   atoms      = (const int*)  d_in[0];
    const float* atoms_mask = (const float*)d_in[1];
    const int*   adjacency  = (const int*)  d_in[2];
    const int*   amino      = (const int*)  d_in[3];
    const float* amino_mask = (const float*)d_in[4];
    const float* E_atom     = (const float*)d_in[5];
    const float* E_amino    = (const float*)d_in[6];
    const float* W_gat      = (const float*)d_in[7];
    const float* a_gat      = (const float*)d_in[8];
    const float* W_go       = (const float*)d_in[9];
    const float* a_go       = (const float*)d_in[10];
    const float* W_comp_w   = (const float*)d_in[11];
    const float* W_comp_b   = (const float*)d_in[12];
    const float* conv_w     = (const float*)d_in[13];
    const float* conv_b     = (const float*)d_in[14];
    const float* W_att_w    = (const float*)d_in[15];
    const float* W_att_b    = (const float*)d_in[16];
    const float* pred_w     = (const float*)d_in[17];
    const float* pred_b     = (const float*)d_in[18];
    float* outp = (float*)d_out;

    float *p_av, *p_Wh, *p_src, *p_dst, *p_multi, *p_Wh2, *p_src2, *p_dst2;
    float *p_x, *p_atoms_vec, *p_a_v, *p_pv0, *p_pv1, *p_pvatt, *p_comp, *p_prot;
    cudaGetSymbolAddress((void**)&p_av, g_av);
    cudaGetSymbolAddress((void**)&p_Wh, g_Wh);
    cudaGetSymbolAddress((void**)&p_src, g_src);
    cudaGetSymbolAddress((void**)&p_dst, g_dst);
    cudaGetSymbolAddress((void**)&p_multi, g_multi);
    cudaGetSymbolAddress((void**)&p_Wh2, g_Wh2);
    cudaGetSymbolAddress((void**)&p_src2, g_src2);
    cudaGetSymbolAddress((void**)&p_dst2, g_dst2);
    cudaGetSymbolAddress((void**)&p_x, g_x);
    cudaGetSymbolAddress((void**)&p_atoms_vec, g_atoms_vec);
    cudaGetSymbolAddress((void**)&p_a_v, g_a_v);
    cudaGetSymbolAddress((void**)&p_pv0, g_pv0);
    cudaGetSymbolAddress((void**)&p_pv1, g_pv1);
    cudaGetSymbolAddress((void**)&p_pvatt, g_pvatt);
    cudaGetSymbolAddress((void**)&p_comp, g_comp);
    cudaGetSymbolAddress((void**)&p_prot, g_prot);

    // opt into >48KB dynamic smem for attention kernels (idempotent, capture-safe)
    const int smem64  = 32*513*4 + 64*64*4;    // 82048
    const int smem128 = 32*513*4 + 64*128*4;   // 98432
    cudaFuncSetAttribute(attn_kernel<64>,  cudaFuncAttributeMaxDynamicSharedMemorySize, smem64);
    cudaFuncSetAttribute(attn_kernel<128>, cudaFuncAttributeMaxDynamicSharedMemorySize, smem128);

    // 1. embeddings
    gather_embed<<<B_*NA, 128>>>(atoms, E_atom, p_av, CD);
    gather_embed<<<B_*LA, 128>>>(amino, E_amino, p_pv0, CD);

    // 2. layer-1 GAT: Wh = av @ W_gat[h]  (64 batches = 4 heads x 16)
    sgemm64<false,0><<<dim3(1,8,NH*B_), 256>>>(p_av, W_gat, nullptr, p_Wh,
        NA, GD, CD, (size_t)NA*CD, B_, (size_t)CD*GD, B_, (size_t)NA*GD);
    srcdst_kernel<GD><<<(NH*B_*NA)/8, 256>>>(p_Wh, a_gat, p_src, p_dst, B_*NA, 2*GD);
    attn_kernel<GD><<<dim3(NA/32, NH*B_), 256, smem64>>>(p_Wh, p_src, p_dst,
        adjacency, p_multi, NH*GD, B_);

    // 3. layer-2 GAT: Wh2 = multi @ W_go
    sgemm64<false,0><<<dim3(2,8,B_), 256>>>(p_multi, W_go, nullptr, p_Wh2,
        NA, CD, NH*GD, (size_t)NA*NH*GD, 0, 0, 1, (size_t)NA*CD);
    srcdst_kernel<CD><<<(B_*NA)/8, 256>>>(p_Wh2, a_go, p_src2, p_dst2, B_*NA, 0);
    attn_kernel<CD><<<dim3(NA/32, B_), 256, smem128>>>(p_Wh2, p_src2, p_dst2,
        adjacency, p_x, CD, B_);

    // 4. atoms_vec = lrelu(x @ Wc^T + bc); a_v = lrelu(atoms_vec @ Wa^T + ba)
    sgemm64<true,1><<<dim3(2,8,B_), 256>>>(p_x, W_comp_w, W_comp_b, p_atoms_vec,
        NA, LT, CD, (size_t)NA*CD, 0, 0, 1, (size_t)NA*LT);
    sgemm64<true,1><<<dim3(2,8,B_), 256>>>(p_atoms_vec, W_att_w, W_att_b, p_a_v,
        NA, LT, LT, (size_t)NA*LT, 0, 0, 1, (size_t)NA*LT);

    // 5. protein conv stack (3 layers, relu, SAME)
    conv11<<<dim3(4,32,B_), dim3(32,32)>>>(p_pv0, conv_w, conv_b, 0, p_pv1);
    conv11<<<dim3(4,32,B_), dim3(32,32)>>>(p_pv1, conv_w, conv_b, 1, p_pv0);
    conv11<<<dim3(4,32,B_), dim3(32,32)>>>(p_pv0, conv_w, conv_b, 2, p_pv1);

    // 6. p_v = lrelu(amino_vec @ Wa^T + ba)
    sgemm64<true,1><<<dim3(2,16,B_), 256>>>(p_pv1, W_att_w, W_att_b, p_pvatt,
        LA, LT, LT, (size_t)LA*LT, 0, 0, 1, (size_t)LA*LT);

    // 7. masked mean pools
    pool_kernel<<<B_, 128>>>(p_a_v, atoms_mask, p_comp, NA);
    pool_kernel<<<B_, 128>>>(p_pvatt, amino_mask, p_prot, LA);

    // 8. head
    final_kernel<<<B_, 256>>>(p_comp, p_prot, pred_w, pred_b, outp);
}

// round 3
// speedup vs baseline: 1.9769x; 1.9769x over previous
#include <cuda_runtime.h>
#include <math.h>

#define B_  16
#define NA  512
#define LA  1024
#define CD  128
#define GD  64
#define NH  4
#define LT  128
#define ALPHA 0.2f

// ---------------- scratch (static device globals; no allocations) -------------
__device__ float g_av[B_*NA*CD];
__device__ float g_Wh[NH*B_*NA*GD];
__device__ float g_src[NH*B_*NA];
__device__ float g_dst[NH*B_*NA];
__device__ float g_multi[B_*NA*NH*GD];
__device__ float g_Wh2[B_*NA*CD];
__device__ float g_src2[B_*NA];
__device__ float g_dst2[B_*NA];
__device__ float g_x[B_*NA*CD];
__device__ float g_atoms_vec[B_*NA*LT];
__device__ float g_a_v[B_*NA*LT];
__device__ float g_pv0[B_*LA*CD];
__device__ float g_pv1[B_*LA*CD];
__device__ float g_pvatt[B_*LA*LT];
__device__ float g_part[B_*16*LT];
__device__ float g_comp[B_*LT];
__device__ float g_prot[B_*LT];

// ---------------- embedding gather -------------------------------------------
__global__ void gather_embed(const int* __restrict__ idx, const float* __restrict__ E,
                             float* __restrict__ out, int dim) {
    int i = blockIdx.x;
    int e = idx[i];
    for (int c = threadIdx.x; c < dim; c += blockDim.x)
        out[(size_t)i*dim + c] = E[(size_t)e*dim + c];
}

// ---------------- SGEMM: C = epi(A @ B(^T)), BM=128 BN=64 BK=16, 8x4 micro ----
// EPI: 0 = none, 1 = bias + leaky_relu
template<bool BT, int EPI>
__global__ __launch_bounds__(256) void sgemm128(
        const float* __restrict__ A, const float* __restrict__ Bm,
        const float* __restrict__ bias, float* __restrict__ C,
        int M, int N, int K,
        size_t aBat, int aMod, size_t bBat, int bDiv, size_t cBat) {
    __shared__ __align__(16) float As[16][128];
    __shared__ __align__(16) float Bs[16][64];
    int z = blockIdx.z;
    A  += (size_t)(aMod ? (z % aMod) : z) * aBat;
    Bm += (size_t)(bDiv ? (z / bDiv) : z) * bBat;
    C  += (size_t)z * cBat;
    int bn = blockIdx.x * 64, bm = blockIdx.y * 128;
    int tid = threadIdx.x;
    int tx = tid & 15, ty = tid >> 4;
    float acc[8][4] = {};
    for (int k0 = 0; k0 < K; k0 += 16) {
        #pragma unroll
        for (int l = 0; l < 2; l++) {
            int e = (tid + l*256) * 4;
            int m = e >> 4, k = e & 15;
            float4 v = *(const float4*)&A[(size_t)(bm + m) * K + k0 + k];
            As[k+0][m] = v.x; As[k+1][m] = v.y; As[k+2][m] = v.z; As[k+3][m] = v.w;
        }
        if (BT) {
            int e = tid * 4;
            int n = e >> 4, k = e & 15;
            float4 v = *(const float4*)&Bm[(size_t)(bn + n) * K + k0 + k];
            Bs[k+0][n] = v.x; Bs[k+1][n] = v.y; Bs[k+2][n] = v.z; Bs[k+3][n] = v.w;
        } else {
            int e = tid * 4;
            int k = e >> 6, n = e & 63;
            *(float4*)&Bs[k][n] = *(const float4*)&Bm[(size_t)(k0 + k) * N + bn + n];
        }
        __syncthreads();
        #pragma unroll
        for (int k = 0; k < 16; k++) {
            float4 a0 = *(const float4*)&As[k][ty*8];
            float4 a1 = *(const float4*)&As[k][ty*8 + 4];
            float4 b4 = *(const float4*)&Bs[k][tx*4];
            float av[8] = {a0.x,a0.y,a0.z,a0.w,a1.x,a1.y,a1.z,a1.w};
            float bv[4] = {b4.x,b4.y,b4.z,b4.w};
            #pragma unroll
            for (int i = 0; i < 8; i++)
                #pragma unroll
                for (int j = 0; j < 4; j++)
                    acc[i][j] += av[i] * bv[j];
        }
        __syncthreads();
    }
    #pragma unroll
    for (int i = 0; i < 8; i++) {
        int m = bm + ty*8 + i;
        float4 v = make_float4(acc[i][0], acc[i][1], acc[i][2], acc[i][3]);
        if (EPI == 1) {
            int n = bn + tx*4;
            v.x += bias[n+0]; v.y += bias[n+1]; v.z += bias[n+2]; v.w += bias[n+3];
            v.x = (v.x >= 0.f) ? v.x : ALPHA*v.x;
            v.y = (v.y >= 0.f) ? v.y : ALPHA*v.y;
            v.z = (v.z >= 0.f) ? v.z : ALPHA*v.z;
            v.w = (v.w >= 0.f) ? v.w : ALPHA*v.w;
        }
        *(float4*)&C[(size_t)m * N + bn + tx*4] = v;
    }
}

// ---------------- src/dst attention dot products ------------------------------
template<int F>
__global__ void srcdst_kernel(const float* __restrict__ Wh, const float* __restrict__ a,
                              float* __restrict__ src, float* __restrict__ dst,
                              int rowsPerHead, int aHeadStride) {
    int gwarp = (blockIdx.x * blockDim.x + threadIdx.x) >> 5;
    int lane = threadIdx.x & 31;
    const float* ar = a + (size_t)(gwarp / rowsPerHead) * aHeadStride;
    const float* w = Wh + (size_t)gwarp * F;
    float s = 0.f, d = 0.f;
    #pragma unroll
    for (int i = lane; i < F; i += 32) {
        float v = w[i];
        s += v * ar[i];
        d += v * ar[F + i];
    }
    #pragma unroll
    for (int o = 16; o; o >>= 1) {
        s += __shfl_xor_sync(0xffffffffu, s, o);
        d += __shfl_xor_sync(0xffffffffu, d, o);
    }
    if (lane == 0) { src[gwarp] = s; dst[gwarp] = d; }
}

// ---------------- fused flash-style GAT attention ----------------------------
// No max-pass (logits tiny), exp only where adj>0, streaming 64-col chunks,
// normalize + elu at the end. 32 rows per block, 256 threads.
template<int F>
__global__ __launch_bounds__(256) void attn_fused(
        const float* __restrict__ Wh, const float* __restrict__ src,
        const float* __restrict__ dst, const int* __restrict__ adj,
        float* __restrict__ out, int outRowStride, int nb) {
    constexpr int TN = F / 32;   // 2 (F=64) or 4 (F=128)
    constexpr int TM = 4;
    __shared__ __align__(16) float wsm[32][64];
    __shared__ __align__(16) float whs[64 * F];
    __shared__ float rowsumS[32];
    int hb = blockIdx.y;
    int b = hb % nb, h = hb / nb;
    const float* WhB  = Wh  + (size_t)hb * NA * F;
    const float* srcB = src + (size_t)hb * NA;
    const float* dstB = dst + (size_t)hb * NA;
    const int*   adjB = adj + (size_t)b * NA * NA;
    int row0 = blockIdx.x * 32;
    int tid = threadIdx.x;
    // phase A mapping: 8 threads per row, 8 cells each
    int ra = tid >> 3, ga = tid & 7;
    float srow = srcB[row0 + ra];
    const int* arow = adjB + (size_t)(row0 + ra) * NA + ga * 8;
    // phase B mapping: 8 warps x 4 rows, 32 lanes x TN cols
    int tx = tid & 31, ty = tid >> 5;
    float acc[TM][TN] = {};
    float psum = 0.f;

    for (int jc = 0; jc < NA; jc += 64) {
        // ---- phase A: masked exp(leaky(src+dst)) for 8 cells ----
        const int4* ap = (const int4*)(arow + jc);
        int4 a0 = ap[0], a1 = ap[1];
        const float4* dp = (const float4*)(dstB + jc + ga*8);
        float4 d0 = dp[0], d1 = dp[1];
        int   am[8] = {a0.x,a0.y,a0.z,a0.w,a1.x,a1.y,a1.z,a1.w};
        float dv[8] = {d0.x,d0.y,d0.z,d0.w,d1.x,d1.y,d1.z,d1.w};
        float w[8];
        #pragma unroll
        for (int k = 0; k < 8; k++) {
            float t = srow + dv[k];
            t = (t >= 0.f) ? t : ALPHA * t;
            float ex = (am[k] > 0) ? __expf(t) : 0.f;
            w[k] = ex;
            psum += ex;
        }
        *(float4*)&wsm[ra][ga*8]     = make_float4(w[0], w[1], w[2], w[3]);
        *(float4*)&wsm[ra][ga*8 + 4] = make_float4(w[4], w[5], w[6], w[7]);
        // ---- stage Wh chunk (contiguous 64*F floats) ----
        const float4* gsrc = (const float4*)(WhB + (size_t)jc * F);
        float4* sdst = (float4*)whs;
        #pragma unroll
        for (int l = 0; l < (64 * F / 4) / 256; l++)
            sdst[tid + l*256] = gsrc[tid + l*256];
        __syncthreads();
        // ---- phase B: acc += w[32][64] @ whs[64][F] ----
        #pragma unroll 4
        for (int jj = 0; jj < 64; jj += 4) {
            float4 wr[TM];
            #pragma unroll
            for (int t = 0; t < TM; t++)
                wr[t] = *(const float4*)&wsm[ty*TM + t][jj];
            #pragma unroll
            for (int u = 0; u < 4; u++) {
                float wv[TN];
                const float* wp = whs + (jj + u) * F + tx * TN;
                if constexpr (TN == 2) {
                    float2 t2 = *(const float2*)wp; wv[0] = t2.x; wv[1] = t2.y;
                } else {
                    float4 t4 = *(const float4*)wp; wv[0]=t4.x; wv[1]=t4.y; wv[2]=t4.z; wv[3]=t4.w;
                }
                #pragma unroll
                for (int t = 0; t < TM; t++) {
                    float wrv = ((const float*)&wr[t])[u];
                    #pragma unroll
                    for (int n = 0; n < TN; n++)
                        acc[t][n] += wrv * wv[n];
                }
            }
        }
        __syncthreads();
    }
    // row sums
    #pragma unroll
    for (int o = 4; o; o >>= 1) psum += __shfl_down_sync(0xffffffffu, psum, o, 8);
    if (ga == 0) rowsumS[ra] = psum;
    __syncthreads();
    // normalize + elu + store
    int colOff = h * F;
    #pragma unroll
    for (int t = 0; t < TM; t++) {
        int r = ty*TM + t;
        float inv = 1.f / rowsumS[r];
        float* op = out + ((size_t)b * NA + row0 + r) * outRowStride + colOff + tx*TN;
        #pragma unroll
        for (int n = 0; n < TN; n++) {
            float v = acc[t][n] * inv;
            v = (v > 0.f) ? v : expm1f(v);
            op[n] = v;
        }
    }
}

// ---------------- 11x11 conv, SAME pad, relu, 4 outputs/thread ----------------
__global__ __launch_bounds__(256) void conv11r(const float* __restrict__ in,
        const float* __restrict__ wconv, const float* __restrict__ bconv,
        int layer, float* __restrict__ out) {
    __shared__ float tile[42][42];
    __shared__ float ws[121];
    int b = blockIdx.z, ly0 = blockIdx.y * 32, lx0 = blockIdx.x * 32;
    int tid = threadIdx.x;
    int tx = tid & 31, ty = tid >> 5;   // 32 x 8; each thread 4 rows
    if (tid < 121) ws[tid] = wconv[layer*121 + tid];
    const float* inb = in + (size_t)b * LA * CD;
    for (int e = tid; e < 42*42; e += 256) {
        int sy = e / 42, sx = e % 42;
        int gy = ly0 + sy - 5, gx = lx0 + sx - 5;
        tile[sy][sx] = (gy >= 0 && gy < LA && gx >= 0 && gx < CD) ? inb[(size_t)gy*CD + gx] : 0.f;
    }
    __syncthreads();
    float bz = bconv[layer];
    float acc[4] = {bz, bz, bz, bz};
    #pragma unroll
    for (int kx = 0; kx < 11; kx++) {
        float v[14];
        #pragma unroll
        for (int r = 0; r < 14; r++) v[r] = tile[ty*4 + r][tx + kx];
        #pragma unroll
        for (int ky = 0; ky < 11; ky++) {
            float wv = ws[ky*11 + kx];
            #pragma unroll
            for (int i = 0; i < 4; i++) acc[i] += v[ky + i] * wv;
        }
    }
    #pragma unroll
    for (int i = 0; i < 4; i++)
        out[(size_t)b*LA*CD + (size_t)(ly0 + ty*4 + i)*CD + lx0 + tx] = fmaxf(acc[i], 0.f);
}

// ---------------- masked mean pool, two-stage ---------------------------------
__global__ void pool_stage1(const float* __restrict__ v, const float* __restrict__ mask,
                            float* __restrict__ part, int n, int chunks) {
    int b = blockIdx.x, ch = blockIdx.y, c = threadIdx.x;  // 128 threads
    int i0 = ch * 64;
    const float* vb = v + ((size_t)b * n + i0) * LT;
    const float* mb = mask + (size_t)b * n + i0;
    float acc = 0.f;
    #pragma unroll 8
    for (int i = 0; i < 64; i++) acc += vb[(size_t)i*LT + c] * mb[i];
    part[((size_t)b * chunks + ch) * LT + c] = acc;
}
__global__ void pool_stage2(const float* __restrict__ part, const float* __restrict__ mask,
                            float* __restrict__ out, int n, int chunks) {
    __shared__ float red[128];
    int b = blockIdx.x, c = threadIdx.x;
    float acc = 0.f;
    for (int ch = 0; ch < chunks; ch++) acc += part[((size_t)b*chunks + ch)*LT + c];
    float ms = 0.f;
    for (int i = c; i < n; i += 128) ms += mask[(size_t)b*n + i];
    red[c] = ms;
    __syncthreads();
    for (int o = 64; o; o >>= 1) { if (c < o) red[c] += red[c + o]; __syncthreads(); }
    out[b*LT + c] = acc / red[0];
}

// ---------------- final head: 2x leaky_relu + dot -----------------------------
__global__ void final_kernel(const float* __restrict__ comp, const float* __restrict__ prot,
                             const float* __restrict__ pw, const float* __restrict__ pb,
                             float* __restrict__ out) {
    __shared__ float red[256];
    int b = blockIdx.x, t = threadIdx.x;
    float v = (t < 128) ? comp[b*128 + t] : prot[b*128 + t - 128];
    v = (v >= 0.f) ? v : ALPHA * v;
    v = (v >= 0.f) ? v : ALPHA * v;
    red[t] = v * pw[t];
    __syncthreads();
    for (int o = 128; o; o >>= 1) {
        if (t < o) red[t] += red[t + o];
        __syncthreads();
    }
    if (t == 0) out[b] = red[0] + pb[0];
}

// ------------------------------------------------------------------------------
extern "C" void kernel_launch(void* const* d_in, const int* in_sizes, int n_in,
                              void* d_out, int out_size) {
    const int*   atoms      = (const int*)  d_in[0];
    const float* atoms_mask = (const float*)d_in[1];
    const int*   adjacency  = (const int*)  d_in[2];
    const int*   amino      = (const int*)  d_in[3];
    const float* amino_mask = (const float*)d_in[4];
    const float* E_atom     = (const float*)d_in[5];
    const float* E_amino    = (const float*)d_in[6];
    const float* W_gat      = (const float*)d_in[7];
    const float* a_gat      = (const float*)d_in[8];
    const float* W_go       = (const float*)d_in[9];
    const float* a_go       = (const float*)d_in[10];
    const float* W_comp_w   = (const float*)d_in[11];
    const float* W_comp_b   = (const float*)d_in[12];
    const float* conv_w     = (const float*)d_in[13];
    const float* conv_b     = (const float*)d_in[14];
    const float* W_att_w    = (const float*)d_in[15];
    const float* W_att_b    = (const float*)d_in[16];
    const float* pred_w     = (const float*)d_in[17];
    const float* pred_b     = (const float*)d_in[18];
    float* outp = (float*)d_out;

    float *p_av, *p_Wh, *p_src, *p_dst, *p_multi, *p_Wh2, *p_src2, *p_dst2;
    float *p_x, *p_atoms_vec, *p_a_v, *p_pv0, *p_pv1, *p_pvatt, *p_part, *p_comp, *p_prot;
    cudaGetSymbolAddress((void**)&p_av, g_av);
    cudaGetSymbolAddress((void**)&p_Wh, g_Wh);
    cudaGetSymbolAddress((void**)&p_src, g_src);
    cudaGetSymbolAddress((void**)&p_dst, g_dst);
    cudaGetSymbolAddress((void**)&p_multi, g_multi);
    cudaGetSymbolAddress((void**)&p_Wh2, g_Wh2);
    cudaGetSymbolAddress((void**)&p_src2, g_src2);
    cudaGetSymbolAddress((void**)&p_dst2, g_dst2);
    cudaGetSymbolAddress((void**)&p_x, g_x);
    cudaGetSymbolAddress((void**)&p_atoms_vec, g_atoms_vec);
    cudaGetSymbolAddress((void**)&p_a_v, g_a_v);
    cudaGetSymbolAddress((void**)&p_pv0, g_pv0);
    cudaGetSymbolAddress((void**)&p_pv1, g_pv1);
    cudaGetSymbolAddress((void**)&p_pvatt, g_pvatt);
    cudaGetSymbolAddress((void**)&p_part, g_part);
    cudaGetSymbolAddress((void**)&p_comp, g_comp);
    cudaGetSymbolAddress((void**)&p_prot, g_prot);

    // 1. embeddings
    gather_embed<<<B_*NA, 128>>>(atoms, E_atom, p_av, CD);
    gather_embed<<<B_*LA, 128>>>(amino, E_amino, p_pv0, CD);

    // 2. layer-1 GAT: Wh = av @ W_gat[h]  (64 batches = 4 heads x 16)
    sgemm128<false,0><<<dim3(1, 4, NH*B_), 256>>>(p_av, W_gat, nullptr, p_Wh,
        NA, GD, CD, (size_t)NA*CD, B_, (size_t)CD*GD, B_, (size_t)NA*GD);
    srcdst_kernel<GD><<<(NH*B_*NA)/8, 256>>>(p_Wh, a_gat, p_src, p_dst, B_*NA, 2*GD);
    attn_fused<GD><<<dim3(NA/32, NH*B_), 256>>>(p_Wh, p_src, p_dst,
        adjacency, p_multi, NH*GD, B_);

    // 3. layer-2 GAT: Wh2 = multi @ W_go
    sgemm128<false,0><<<dim3(2, 4, B_), 256>>>(p_multi, W_go, nullptr, p_Wh2,
        NA, CD, NH*GD, (size_t)NA*NH*GD, 0, 0, 1, (size_t)NA*CD);
    srcdst_kernel<CD><<<(B_*NA)/8, 256>>>(p_Wh2, a_go, p_src2, p_dst2, B_*NA, 0);
    attn_fused<CD><<<dim3(NA/32, B_), 256>>>(p_Wh2, p_src2, p_dst2,
        adjacency, p_x, CD, B_);

    // 4. atoms_vec = lrelu(x @ Wc^T + bc); a_v = lrelu(atoms_vec @ Wa^T + ba)
    sgemm128<true,1><<<dim3(2, 4, B_), 256>>>(p_x, W_comp_w, W_comp_b, p_atoms_vec,
        NA, LT, CD, (size_t)NA*CD, 0, 0, 1, (size_t)NA*LT);
    sgemm128<true,1><<<dim3(2, 4, B_), 256>>>(p_atoms_vec, W_att_w, W_att_b, p_a_v,
        NA, LT, LT, (size_t)NA*LT, 0, 0, 1, (size_t)NA*LT);

    // 5. protein conv stack (3 layers, relu, SAME)
    conv11r<<<dim3(4, 32, B_), 256>>>(p_pv0, conv_w, conv_b, 0, p_pv1);
    conv11r<<<dim3(4, 32, B_), 256>>>(p_pv1, conv_w, conv_b, 1, p_pv0);
    conv11r<<<dim3(4, 32, B_), 256>>>(p_pv0, conv_w, conv_b, 2, p_pv1);

    // 6. p_v = lrelu(amino_vec @ Wa^T + ba)
    sgemm128<true,1><<<dim3(2, 8, B_), 256>>>(p_pv1, W_att_w, W_att_b, p_pvatt,
        LA, LT, LT, (size_t)LA*LT, 0, 0, 1, (size_t)LA*LT);

    // 7. masked mean pools (two-stage, full-chip)
    pool_stage1<<<dim3(B_, NA/64), 128>>>(p_a_v, atoms_mask, p_part, NA, NA/64);
    pool_stage2<<<B_, 128>>>(p_part, atoms_mask, p_comp, NA, NA/64);
    pool_stage1<<<dim3(B_, LA/64), 128>>>(p_pvatt, amino_mask, p_part, LA, LA/64);
    pool_stage2<<<B_, 128>>>(p_part, amino_mask, p_prot, LA, LA/64);

    // 8. head
    final_kernel<<<B_, 256>>>(p_comp, p_prot, pred_w, pred_b, outp);
}

// round 4
// speedup vs baseline: 2.1600x; 1.0926x over previous
#include <cuda_runtime.h>
#include <math.h>

#define B_  16
#define NA  512
#define LA  1024
#define CD  128
#define GD  64
#define NH  4
#define LT  128
#define ALPHA 0.2f

typedef unsigned long long u64;

static __device__ __forceinline__ u64 fma2(u64 a, u64 b, u64 c) {
    u64 d;
    asm("fma.rn.f32x2 %0, %1, %2, %3;" : "=l"(d) : "l"(a), "l"(b), "l"(c));
    return d;
}
static __device__ __forceinline__ u64 pack2(float lo, float hi) {
    u64 r;
    asm("mov.b64 %0, {%1, %2};" : "=l"(r) : "f"(lo), "f"(hi));
    return r;
}
static __device__ __forceinline__ float2 u2f(u64 v) {
    float2 r;
    asm("mov.b64 {%0, %1}, %2;" : "=f"(r.x), "=f"(r.y) : "l"(v));
    return r;
}

// ---------------- scratch (static device globals; no allocations) -------------
__device__ float g_Wh[NH*B_*NA*GD];
__device__ float g_src[NH*B_*NA];
__device__ float g_dst[NH*B_*NA];
__device__ float g_multi[B_*NA*NH*GD];
__device__ float g_Wh2[B_*NA*CD];
__device__ float g_src2[B_*NA];
__device__ float g_dst2[B_*NA];
__device__ float g_x[B_*NA*CD];
__device__ float g_atoms_vec[B_*NA*LT];
__device__ float g_pv0[B_*LA*CD];
__device__ float g_pv1[B_*LA*CD];
__device__ float g_part[B_*LT];
__device__ float g_part2[B_*LT];

// ---------------- SGEMM with f32x2 K-paired inner loop ------------------------
// BM=128 BN=64 BK=16, 256 threads, 8x4 microtile; column map n = tx + 16*j.
// EPI: 0 none, 1 bias+leaky_relu (store), 2 bias+leaky_relu + masked column-sum
//      into part[] (NO store).  GATHER: A rows via gidx into embedding table.
//      SRCDST: also emit src/dst dot products with avec (requires N == BN).
template<bool BT, int EPI, bool GATHER, bool SRCDST>
__global__ __launch_bounds__(256) void sgemmX(
        const float* __restrict__ A, const float* __restrict__ Bm,
        const float* __restrict__ bias, float* __restrict__ C,
        const int* __restrict__ gidx,
        const float* __restrict__ avec, float* __restrict__ srcO, float* __restrict__ dstO,
        const float* __restrict__ mask, float* __restrict__ part,
        int M, int N, int K,
        size_t aBat, int aMod, size_t bBat, int bDiv, size_t cBat) {
    __shared__ __align__(16) float As_t[128*16];
    __shared__ __align__(16) float Bs_t[64*20];
    int z = blockIdx.z;
    int zb = aMod ? (z % aMod) : z;
    if (!GATHER) A += (size_t)zb * aBat;
    Bm += (size_t)(bDiv ? (z / bDiv) : z) * bBat;
    C  += (size_t)z * cBat;
    int bn = blockIdx.x * 64, bm = blockIdx.y * 128;
    int tid = threadIdx.x;
    int tx = tid & 15, ty = tid >> 4;
    u64 acc[8][4] = {};
    for (int k0 = 0; k0 < K; k0 += 16) {
        #pragma unroll
        for (int l = 0; l < 2; l++) {
            int e = tid + l*256;
            int m = e >> 2, k4 = (e & 3) * 4;
            const float* sp;
            if (GATHER) {
                int row = gidx[(size_t)zb * M + bm + m];
                sp = &A[(size_t)row * K + k0 + k4];
            } else {
                sp = &A[(size_t)(bm + m) * K + k0 + k4];
            }
            *(float4*)&As_t[m*16 + k4] = *(const float4*)sp;
        }
        if (BT) {
            int n = tid >> 2, k4 = (tid & 3) * 4;
            *(float4*)&Bs_t[n*20 + k4] = *(const float4*)&Bm[(size_t)(bn + n)*K + k0 + k4];
        } else {
            int k = tid >> 4, n4 = (tid & 15) * 4;
            float4 v = *(const float4*)&Bm[(size_t)(k0 + k)*N + bn + n4];
            Bs_t[(n4+0)*20 + k] = v.x;
            Bs_t[(n4+1)*20 + k] = v.y;
            Bs_t[(n4+2)*20 + k] = v.z;
            Bs_t[(n4+3)*20 + k] = v.w;
        }
        __syncthreads();
        #pragma unroll
        for (int q = 0; q < 4; q++) {
            ulonglong2 aQ[8];
            #pragma unroll
            for (int i = 0; i < 8; i++)
                aQ[i] = *(const ulonglong2*)&As_t[(ty*8 + i)*16 + q*4];
            ulonglong2 bQ[4];
            #pragma unroll
            for (int j = 0; j < 4; j++)
                bQ[j] = *(const ulonglong2*)&Bs_t[(tx + 16*j)*20 + q*4];
            #pragma unroll
            for (int i = 0; i < 8; i++)
                #pragma unroll
                for (int j = 0; j < 4; j++) {
                    acc[i][j] = fma2(aQ[i].x, bQ[j].x, acc[i][j]);
                    acc[i][j] = fma2(aQ[i].y, bQ[j].y, acc[i][j]);
                }
        }
        __syncthreads();
    }
    // collapse pairs
    float vv[8][4];
    #pragma unroll
    for (int i = 0; i < 8; i++)
        #pragma unroll
        for (int j = 0; j < 4; j++) {
            float2 p = u2f(acc[i][j]);
            float v = p.x + p.y;
            if (EPI >= 1) {
                v += bias[bn + tx + 16*j];
                v = (v >= 0.f) ? v : ALPHA * v;
            }
            vv[i][j] = v;
        }
    if (EPI == 2) {
        const float* maskB = mask + (size_t)z * M;
        float cs[4] = {};
        #pragma unroll
        for (int i = 0; i < 8; i++) {
            float mk = maskB[bm + ty*8 + i];
            #pragma unroll
            for (int j = 0; j < 4; j++) cs[j] += vv[i][j] * mk;
        }
        float* sred = As_t;  // reuse: [16][64]
        #pragma unroll
        for (int j = 0; j < 4; j++) sred[ty*64 + tx + 16*j] = cs[j];
        __syncthreads();
        if (tid < 64) {
            float s = 0.f;
            #pragma unroll
            for (int t = 0; t < 16; t++) s += sred[t*64 + tid];
            atomicAdd(&part[(size_t)z * LT + bn + tid], s);
        }
        return;
    }
    #pragma unroll
    for (int i = 0; i < 8; i++) {
        int m = bm + ty*8 + i;
        #pragma unroll
        for (int j = 0; j < 4; j++)
            C[(size_t)m * N + bn + tx + 16*j] = vv[i][j];
    }
    if (SRCDST) {
        const float* av = avec + (size_t)(bDiv ? (z / bDiv) : 0) * 2 * N;
        float a0[4], a1[4];
        #pragma unroll
        for (int j = 0; j < 4; j++) {
            a0[j] = av[bn + tx + 16*j];
            a1[j] = av[N + bn + tx + 16*j];
        }
        #pragma unroll
        for (int i = 0; i < 8; i++) {
            float s = 0.f, d = 0.f;
            #pragma unroll
            for (int j = 0; j < 4; j++) {
                s += vv[i][j] * a0[j];
                d += vv[i][j] * a1[j];
            }
            #pragma unroll
            for (int o = 8; o; o >>= 1) {
                s += __shfl_xor_sync(0xffffffffu, s, o);
                d += __shfl_xor_sync(0xffffffffu, d, o);
            }
            if (tx == 0) {
                int m = bm + ty*8 + i;
                srcO[(size_t)z * M + m] = s;
                dstO[(size_t)z * M + m] = d;
            }
        }
    }
}

// ---------------- src/dst dots (layer 2 only) ---------------------------------
template<int F>
__global__ void srcdst_kernel(const float* __restrict__ Wh, const float* __restrict__ a,
                              float* __restrict__ src, float* __restrict__ dst) {
    int gwarp = (blockIdx.x * blockDim.x + threadIdx.x) >> 5;
    int lane = threadIdx.x & 31;
    const float* w = Wh + (size_t)gwarp * F;
    float s = 0.f, d = 0.f;
    #pragma unroll
    for (int i = lane; i < F; i += 32) {
        float v = w[i];
        s += v * a[i];
        d += v * a[F + i];
    }
    #pragma unroll
    for (int o = 16; o; o >>= 1) {
        s += __shfl_xor_sync(0xffffffffu, s, o);
        d += __shfl_xor_sync(0xffffffffu, d, o);
    }
    if (lane == 0) { src[gwarp] = s; dst[gwarp] = d; }
}

// ---------------- fused GAT attention, f32x2 jj-paired inner loop --------------
// 32 rows/block, 256 threads.  Column map: n = tx + 32*u.
template<int F>
__global__ __launch_bounds__(256) void attn2x(
        const float* __restrict__ Wh, const float* __restrict__ src,
        const float* __restrict__ dst, const int* __restrict__ adj,
        float* __restrict__ out, int outRowStride, int nb) {
    constexpr int TN = F / 32;       // 2 or 4
    constexpr int PAD = 66;
    constexpr int G = 256 / F;       // thread groups for staging
    __shared__ __align__(16) float wsm[32*64];
    __shared__ __align__(16) float whs_t[F*PAD];
    __shared__ float rowsumS[32];
    int hb = blockIdx.y;
    int b = hb % nb, h = hb / nb;
    const float* WhB  = Wh  + (size_t)hb * NA * F;
    const float* srcB = src + (size_t)hb * NA;
    const float* dstB = dst + (size_t)hb * NA;
    const int*   adjB = adj + (size_t)b * NA * NA;
    int row0 = blockIdx.x * 32;
    int tid = threadIdx.x;
    int ra = tid >> 3, ga = tid & 7;
    float srow = srcB[row0 + ra];
    const int* arow = adjB + (size_t)(row0 + ra) * NA + ga * 8;
    int tx = tid & 31, ty = tid >> 5;
    int n_s = tid % F, jg = tid / F;
    u64 acc[4][TN] = {};
    float psum = 0.f;

    for (int jc = 0; jc < NA; jc += 64) {
        // ---- phase A: masked exp(leaky(src+dst)) -> wsm ----
        const int4* ap = (const int4*)(arow + jc);
        int4 A0 = ap[0], A1 = ap[1];
        const float4* dp = (const float4*)(dstB + jc + ga*8);
        float4 d0 = dp[0], d1 = dp[1];
        int   am[8] = {A0.x,A0.y,A0.z,A0.w,A1.x,A1.y,A1.z,A1.w};
        float dv[8] = {d0.x,d0.y,d0.z,d0.w,d1.x,d1.y,d1.z,d1.w};
        float w[8];
        #pragma unroll
        for (int k = 0; k < 8; k++) {
            float t = srow + dv[k];
            t = (t >= 0.f) ? t : ALPHA * t;
            float ex = (am[k] > 0) ? __expf(t) : 0.f;
            w[k] = ex;
            psum += ex;
        }
        *(float4*)&wsm[ra*64 + ga*8]     = make_float4(w[0], w[1], w[2], w[3]);
        *(float4*)&wsm[ra*64 + ga*8 + 4] = make_float4(w[4], w[5], w[6], w[7]);
        // ---- stage Wh chunk transposed: whs_t[n][jj] ----
        #pragma unroll
        for (int l = 0; l < 64/(G*4); l++) {
            int jj0 = (jg + l*G) * 4;
            const float* gp = WhB + (size_t)(jc + jj0) * F + n_s;
            float t0 = gp[0], t1 = gp[F], t2 = gp[2*F], t3 = gp[3*F];
            *(u64*)&whs_t[n_s*PAD + jj0]     = pack2(t0, t1);
            *(u64*)&whs_t[n_s*PAD + jj0 + 2] = pack2(t2, t3);
        }
        __syncthreads();
        // ---- acc += w[32][64] @ whT[64][F], jj-paired f32x2 ----
        #pragma unroll
        for (int jb = 0; jb < 8; jb++) {
            ulonglong2 wrA[4], wrB[4];
            #pragma unroll
            for (int t = 0; t < 4; t++) {
                wrA[t] = *(const ulonglong2*)&wsm[(ty*4 + t)*64 + jb*8];
                wrB[t] = *(const ulonglong2*)&wsm[(ty*4 + t)*64 + jb*8 + 4];
            }
            #pragma unroll
            for (int p = 0; p < 4; p++) {
                #pragma unroll
                for (int u = 0; u < TN; u++) {
                    u64 wv = *(const u64*)&whs_t[(tx + 32*u)*PAD + jb*8 + p*2];
                    #pragma unroll
                    for (int t = 0; t < 4; t++) {
                        u64 wp = (p == 0) ? wrA[t].x : (p == 1) ? wrA[t].y
                               : (p == 2) ? wrB[t].x : wrB[t].y;
                        acc[t][u] = fma2(wp, wv, acc[t][u]);
                    }
                }
            }
        }
        __syncthreads();
    }
    // row sums (8 threads per row)
    #pragma unroll
    for (int o = 4; o; o >>= 1) psum += __shfl_down_sync(0xffffffffu, psum, o, 8);
    if (ga == 0) rowsumS[ra] = psum;
    __syncthreads();
    // normalize + elu + store
    int colOff = h * F;
    #pragma unroll
    for (int t = 0; t < 4; t++) {
        int r = ty*4 + t;
        float inv = 1.f / rowsumS[r];
        float* op = out + ((size_t)b * NA + row0 + r) * outRowStride + colOff;
        #pragma unroll
        for (int u = 0; u < TN; u++) {
            float2 pr = u2f(acc[t][u]);
            float v = (pr.x + pr.y) * inv;
            v = (v > 0.f) ? v : expm1f(v);
            op[tx + 32*u] = v;
        }
    }
}

// ---------------- 11x11 conv, SAME pad, relu, 4 outputs/thread ----------------
template<bool G>
__global__ __launch_bounds__(256) void conv11r(const float* __restrict__ in,
        const int* __restrict__ gidx, const float* __restrict__ wconv,
        const float* __restrict__ bconv, int layer, float* __restrict__ out) {
    __shared__ float tile[42][42];
    __shared__ float ws[121];
    int b = blockIdx.z, ly0 = blockIdx.y * 32, lx0 = blockIdx.x * 32;
    int tid = threadIdx.x;
    int tx = tid & 31, ty = tid >> 5;
    if (tid < 121) ws[tid] = wconv[layer*121 + tid];
    const float* inb = in + (size_t)b * LA * CD;
    const int* gb = gidx + (size_t)b * LA;
    for (int e = tid; e < 42*42; e += 256) {
        int sy = e / 42, sx = e % 42;
        int gy = ly0 + sy - 5, gx = lx0 + sx - 5;
        float val = 0.f;
        if (gy >= 0 && gy < LA && gx >= 0 && gx < CD) {
            if (G) val = in[(size_t)gb[gy]*CD + gx];
            else   val = inb[(size_t)gy*CD + gx];
        }
        tile[sy][sx] = val;
    }
    __syncthreads();
    float bz = bconv[layer];
    float acc[4] = {bz, bz, bz, bz};
    #pragma unroll
    for (int kx = 0; kx < 11; kx++) {
        float v[14];
        #pragma unroll
        for (int r = 0; r < 14; r++) v[r] = tile[ty*4 + r][tx + kx];
        #pragma unroll
        for (int ky = 0; ky < 11; ky++) {
            float wv = ws[ky*11 + kx];
            #pragma unroll
            for (int i = 0; i < 4; i++) acc[i] += v[ky + i] * wv;
        }
    }
    #pragma unroll
    for (int i = 0; i < 4; i++)
        out[(size_t)b*LA*CD + (size_t)(ly0 + ty*4 + i)*CD + lx0 + tx] = fmaxf(acc[i], 0.f);
}

// ---------------- finalize: pools -> lrelu^2 -> dot ---------------------------
__global__ void finalize(const float* __restrict__ part, const float* __restrict__ part2,
                         const float* __restrict__ amask, const float* __restrict__ pmask,
                         const float* __restrict__ pw, const float* __restrict__ pb,
                         float* __restrict__ out) {
    __shared__ float redA[256], redB[256], red[256];
    int b = blockIdx.x, t = threadIdx.x;
    float msA = 0.f, msP = 0.f;
    for (int i = t; i < NA; i += 256) msA += amask[(size_t)b*NA + i];
    for (int i = t; i < LA; i += 256) msP += pmask[(size_t)b*LA + i];
    redA[t] = msA; redB[t] = msP;
    __syncthreads();
    for (int o = 128; o; o >>= 1) {
        if (t < o) { redA[t] += redA[t+o]; redB[t] += redB[t+o]; }
        __syncthreads();
    }
    float v = (t < 128) ? part[b*LT + t] / redA[0] : part2[b*LT + (t - 128)] / redB[0];
    v = (v >= 0.f) ? v : ALPHA * v;
    v = (v >= 0.f) ? v : ALPHA * v;
    red[t] = v * pw[t];
    __syncthreads();
    for (int o = 128; o; o >>= 1) {
        if (t < o) red[t] += red[t + o];
        __syncthreads();
    }
    if (t == 0) out[b] = red[0] + pb[0];
}

// ------------------------------------------------------------------------------
extern "C" void kernel_launch(void* const* d_in, const int* in_sizes, int n_in,
                              void* d_out, int out_size) {
    const int*   atoms      = (const int*)  d_in[0];
    const float* atoms_mask = (const float*)d_in[1];
    const int*   adjacency  = (const int*)  d_in[2];
    const int*   amino      = (const int*)  d_in[3];
    const float* amino_mask = (const float*)d_in[4];
    const float* E_atom     = (const float*)d_in[5];
    const float* E_amino    = (const float*)d_in[6];
    const float* W_gat      = (const float*)d_in[7];
    const float* a_gat      = (const float*)d_in[8];
    const float* W_go       = (const float*)d_in[9];
    const float* a_go       = (const float*)d_in[10];
    const float* W_comp_w   = (const float*)d_in[11];
    const float* W_comp_b   = (const float*)d_in[12];
    const float* conv_w     = (const float*)d_in[13];
    const float* conv_b     = (const float*)d_in[14];
    const float* W_att_w    = (const float*)d_in[15];
    const float* W_att_b    = (const float*)d_in[16];
    const float* pred_w     = (const float*)d_in[17];
    const float* pred_b     = (const float*)d_in[18];
    float* outp = (float*)d_out;

    float *p_Wh, *p_src, *p_dst, *p_multi, *p_Wh2, *p_src2, *p_dst2;
    float *p_x, *p_atoms_vec, *p_pv0, *p_pv1, *p_part, *p_part2;
    cudaGetSymbolAddress((void**)&p_Wh, g_Wh);
    cudaGetSymbolAddress((void**)&p_src, g_src);
    cudaGetSymbolAddress((void**)&p_dst, g_dst);
    cudaGetSymbolAddress((void**)&p_multi, g_multi);
    cudaGetSymbolAddress((void**)&p_Wh2, g_Wh2);
    cudaGetSymbolAddress((void**)&p_src2, g_src2);
    cudaGetSymbolAddress((void**)&p_dst2, g_dst2);
    cudaGetSymbolAddress((void**)&p_x, g_x);
    cudaGetSymbolAddress((void**)&p_atoms_vec, g_atoms_vec);
    cudaGetSymbolAddress((void**)&p_pv0, g_pv0);
    cudaGetSymbolAddress((void**)&p_pv1, g_pv1);
    cudaGetSymbolAddress((void**)&p_part, g_part);
    cudaGetSymbolAddress((void**)&p_part2, g_part2);

    // zero pooled partials (graph-capturable memset nodes)
    cudaMemsetAsync(p_part,  0, B_*LT*sizeof(float));
    cudaMemsetAsync(p_part2, 0, B_*LT*sizeof(float));

    // 1. layer-1 GAT projection: Wh = gather(E_atom,atoms) @ W_gat[h], fused src/dst
    sgemmX<false,0,true,true><<<dim3(1,4,NH*B_), 256>>>(
        E_atom, W_gat, nullptr, p_Wh, atoms, a_gat, p_src, p_dst, nullptr, nullptr,
        NA, GD, CD, 0, B_, (size_t)CD*GD, B_, (size_t)NA*GD);
    attn2x<GD><<<dim3(NA/32, NH*B_), 256>>>(p_Wh, p_src, p_dst,
        adjacency, p_multi, NH*GD, B_);

    // 2. layer-2 GAT: Wh2 = multi @ W_go
    sgemmX<false,0,false,false><<<dim3(2,4,B_), 256>>>(
        p_multi, W_go, nullptr, p_Wh2, nullptr, nullptr, nullptr, nullptr, nullptr, nullptr,
        NA, CD, NH*GD, (size_t)NA*NH*GD, 0, 0, 1, (size_t)NA*CD);
    srcdst_kernel<CD><<<(B_*NA)/8, 256>>>(p_Wh2, a_go, p_src2, p_dst2);
    attn2x<CD><<<dim3(NA/32, B_), 256>>>(p_Wh2, p_src2, p_dst2,
        adjacency, p_x, CD, B_);

    // 3. atoms_vec = lrelu(x @ Wc^T + bc);  pool(lrelu(atoms_vec @ Wa^T + ba))
    sgemmX<true,1,false,false><<<dim3(2,4,B_), 256>>>(
        p_x, W_comp_w, W_comp_b, p_atoms_vec, nullptr, nullptr, nullptr, nullptr, nullptr, nullptr,
        NA, LT, CD, (size_t)NA*CD, 0, 0, 1, (size_t)NA*LT);
    sgemmX<true,2,false,false><<<dim3(2,4,B_), 256>>>(
        p_atoms_vec, W_att_w, W_att_b, nullptr, nullptr, nullptr, nullptr, nullptr,
        atoms_mask, p_part,
        NA, LT, LT, (size_t)NA*LT, 0, 0, 1, 0);

    // 4. protein conv stack (layer 0 gathers E_amino directly)
    conv11r<true ><<<dim3(4,32,B_), 256>>>(E_amino, amino, conv_w, conv_b, 0, p_pv1);
    conv11r<false><<<dim3(4,32,B_), 256>>>(p_pv1, amino, conv_w, conv_b, 1, p_pv0);
    conv11r<false><<<dim3(4,32,B_), 256>>>(p_pv0, amino, conv_w, conv_b, 2, p_pv1);

    // 5. pool(lrelu(amino_vec @ Wa^T + ba))
    sgemmX<true,2,false,false><<<dim3(2,8,B_), 256>>>(
        p_pv1, W_att_w, W_att_b, nullptr, nullptr, nullptr, nullptr, nullptr,
        amino_mask, p_part2,
        LA, LT, LT, (size_t)LA*LT, 0, 0, 1, 0);

    // 6. finalize: mean pools -> lrelu^2 -> prediction
    finalize<<<B_, 256>>>(p_part, p_part2, atoms_mask, amino_mask, pred_w, pred_b, outp);
}

// round 7
// speedup vs baseline: 2.2491x; 1.0412x over previous
#include <cuda_runtime.h>
#include <math.h>

#define B_  16
#define NA  512
#define LA  1024
#define CD  128
#define GD  64
#define NH  4
#define LT  128
#define ALPHA 0.2f

typedef unsigned long long u64;

static __device__ __forceinline__ u64 fma2(u64 a, u64 b, u64 c) {
    u64 d;
    asm("fma.rn.f32x2 %0, %1, %2, %3;" : "=l"(d) : "l"(a), "l"(b), "l"(c));
    return d;
}
static __device__ __forceinline__ u64 pack2(float lo, float hi) {
    u64 r;
    asm("mov.b64 %0, {%1, %2};" : "=l"(r) : "f"(lo), "f"(hi));
    return r;
}
static __device__ __forceinline__ float2 u2f(u64 v) {
    float2 r;
    asm("mov.b64 {%0, %1}, %2;" : "=f"(r.x), "=f"(r.y) : "l"(v));
    return r;
}

// ---------------- scratch (static device globals; no allocations) -------------
__device__ float g_Wh[NH*B_*NA*GD];
__device__ float g_src[NH*B_*NA];
__device__ float g_dst[NH*B_*NA];
__device__ float g_multi[B_*NA*NH*GD];
__device__ float g_Wh2[B_*NA*CD];
__device__ float g_src2[B_*NA];
__device__ float g_dst2[B_*NA];
__device__ float g_x[B_*NA*CD];
__device__ float g_atoms_vec[B_*NA*LT];
__device__ float g_pv0[B_*LA*CD];
__device__ float g_pv1[B_*LA*CD];
__device__ float g_part[B_*LT];
__device__ float g_part2[B_*LT];

// ---------------- SGEMM with f32x2 K-paired inner loop ------------------------
// BM=128 BN=64 BK=16, 256 threads, 8x4 microtile; column map n = tx + 16*j.
// EPI: 0 none, 1 bias+leaky_relu (store), 2 bias+leaky_relu + masked column-sum
//      into part[] (NO store).  GATHER: A rows via gidx.  SRCDST: atomicAdd
//      partial src/dst dot products with avec (supports N > BN).
template<bool BT, int EPI, bool GATHER, bool SRCDST>
__global__ __launch_bounds__(256) void sgemmX(
        const float* __restrict__ A, const float* __restrict__ Bm,
        const float* __restrict__ bias, float* __restrict__ C,
        const int* __restrict__ gidx,
        const float* __restrict__ avec, float* __restrict__ srcO, float* __restrict__ dstO,
        const float* __restrict__ mask, float* __restrict__ part,
        int M, int N, int K,
        size_t aBat, int aMod, size_t bBat, int bDiv, size_t cBat) {
    __shared__ __align__(16) float As_t[128*16];
    __shared__ __align__(16) float Bs_t[64*20];
    int z = blockIdx.z;
    int zb = aMod ? (z % aMod) : z;
    if (!GATHER) A += (size_t)zb * aBat;
    Bm += (size_t)(bDiv ? (z / bDiv) : z) * bBat;
    C  += (size_t)z * cBat;
    int bn = blockIdx.x * 64, bm = blockIdx.y * 128;
    int tid = threadIdx.x;
    int tx = tid & 15, ty = tid >> 4;
    u64 acc[8][4] = {};
    for (int k0 = 0; k0 < K; k0 += 16) {
        #pragma unroll
        for (int l = 0; l < 2; l++) {
            int e = tid + l*256;
            int m = e >> 2, k4 = (e & 3) * 4;
            const float* sp;
            if (GATHER) {
                int row = gidx[(size_t)zb * M + bm + m];
                sp = &A[(size_t)row * K + k0 + k4];
            } else {
                sp = &A[(size_t)(bm + m) * K + k0 + k4];
            }
            *(float4*)&As_t[m*16 + k4] = *(const float4*)sp;
        }
        if (BT) {
            int n = tid >> 2, k4 = (tid & 3) * 4;
            *(float4*)&Bs_t[n*20 + k4] = *(const float4*)&Bm[(size_t)(bn + n)*K + k0 + k4];
        } else {
            int k = tid >> 4, n4 = (tid & 15) * 4;
            float4 v = *(const float4*)&Bm[(size_t)(k0 + k)*N + bn + n4];
            Bs_t[(n4+0)*20 + k] = v.x;
            Bs_t[(n4+1)*20 + k] = v.y;
            Bs_t[(n4+2)*20 + k] = v.z;
            Bs_t[(n4+3)*20 + k] = v.w;
        }
        __syncthreads();
        #pragma unroll
        for (int q = 0; q < 4; q++) {
            ulonglong2 aQ[8];
            #pragma unroll
            for (int i = 0; i < 8; i++)
                aQ[i] = *(const ulonglong2*)&As_t[(ty*8 + i)*16 + q*4];
            ulonglong2 bQ[4];
            #pragma unroll
            for (int j = 0; j < 4; j++)
                bQ[j] = *(const ulonglong2*)&Bs_t[(tx + 16*j)*20 + q*4];
            #pragma unroll
            for (int i = 0; i < 8; i++)
                #pragma unroll
                for (int j = 0; j < 4; j++) {
                    acc[i][j] = fma2(aQ[i].x, bQ[j].x, acc[i][j]);
                    acc[i][j] = fma2(aQ[i].y, bQ[j].y, acc[i][j]);
                }
        }
        __syncthreads();
    }
    // collapse pairs
    float vv[8][4];
    #pragma unroll
    for (int i = 0; i < 8; i++)
        #pragma unroll
        for (int j = 0; j < 4; j++) {
            float2 p = u2f(acc[i][j]);
            float v = p.x + p.y;
            if (EPI >= 1) {
                v += bias[bn + tx + 16*j];
                v = (v >= 0.f) ? v : ALPHA * v;
            }
            vv[i][j] = v;
        }
    if (EPI == 2) {
        const float* maskB = mask + (size_t)z * M;
        float cs[4] = {};
        #pragma unroll
        for (int i = 0; i < 8; i++) {
            float mk = maskB[bm + ty*8 + i];
            #pragma unroll
            for (int j = 0; j < 4; j++) cs[j] += vv[i][j] * mk;
        }
        float* sred = As_t;  // reuse: [16][64]
        #pragma unroll
        for (int j = 0; j < 4; j++) sred[ty*64 + tx + 16*j] = cs[j];
        __syncthreads();
        if (tid < 64) {
            float s = 0.f;
            #pragma unroll
            for (int t = 0; t < 16; t++) s += sred[t*64 + tid];
            atomicAdd(&part[(size_t)z * LT + bn + tid], s);
        }
        return;
    }
    #pragma unroll
    for (int i = 0; i < 8; i++) {
        int m = bm + ty*8 + i;
        #pragma unroll
        for (int j = 0; j < 4; j++)
            C[(size_t)m * N + bn + tx + 16*j] = vv[i][j];
    }
    if (SRCDST) {
        const float* av = avec + (size_t)(bDiv ? (z / bDiv) : 0) * 2 * N;
        float a0[4], a1[4];
        #pragma unroll
        for (int j = 0; j < 4; j++) {
            a0[j] = av[bn + tx + 16*j];
            a1[j] = av[N + bn + tx + 16*j];
        }
        #pragma unroll
        for (int i = 0; i < 8; i++) {
            float s = 0.f, d = 0.f;
            #pragma unroll
            for (int j = 0; j < 4; j++) {
                s += vv[i][j] * a0[j];
                d += vv[i][j] * a1[j];
            }
            #pragma unroll
            for (int o = 8; o; o >>= 1) {
                s += __shfl_xor_sync(0xffffffffu, s, o);
                d += __shfl_xor_sync(0xffffffffu, d, o);
            }
            if (tx == 0) {
                int m = bm + ty*8 + i;
                atomicAdd(&srcO[(size_t)z * M + m], s);
                atomicAdd(&dstO[(size_t)z * M + m], d);
            }
        }
    }
}

// ---------------- fused GAT attention, f32x2 pair-major (conflict-free) -------
// 32 rows/block, 256 threads.  Column map: n = tx + 32*u.
template<int F>
__global__ __launch_bounds__(256) void attn2x(
        const float* __restrict__ Wh, const float* __restrict__ src,
        const float* __restrict__ dst, const int* __restrict__ adj,
        float* __restrict__ out, int outRowStride, int nb) {
    constexpr int TN = F / 32;       // 2 or 4
    constexpr int G = 256 / F;       // staging groups
    __shared__ __align__(16) float wsm[32*64];
    __shared__ __align__(16) u64 whs_p[32 * F];   // [pair jj/2][n]
    __shared__ float rowsumS[32];
    int hb = blockIdx.y;
    int b = hb % nb, h = hb / nb;
    const float* WhB  = Wh  + (size_t)hb * NA * F;
    const float* srcB = src + (size_t)hb * NA;
    const float* dstB = dst + (size_t)hb * NA;
    const int*   adjB = adj + (size_t)b * NA * NA;
    int row0 = blockIdx.x * 32;
    int tid = threadIdx.x;
    int ra = tid >> 3, ga = tid & 7;
    float srow = srcB[row0 + ra];
    const int* arow = adjB + (size_t)(row0 + ra) * NA + ga * 8;
    int tx = tid & 31, ty = tid >> 5;
    int n_s = tid % F, jg = tid / F;
    u64 acc[4][TN] = {};
    float psum = 0.f;

    for (int jc = 0; jc < NA; jc += 64) {
        // ---- phase A: masked exp(leaky(src+dst)) -> wsm ----
        const int4* ap = (const int4*)(arow + jc);
        int4 A0 = ap[0], A1 = ap[1];
        const float4* dp = (const float4*)(dstB + jc + ga*8);
        float4 d0 = dp[0], d1 = dp[1];
        int   am[8] = {A0.x,A0.y,A0.z,A0.w,A1.x,A1.y,A1.z,A1.w};
        float dv[8] = {d0.x,d0.y,d0.z,d0.w,d1.x,d1.y,d1.z,d1.w};
        float w[8];
        #pragma unroll
        for (int k = 0; k < 8; k++) {
            float t = srow + dv[k];
            t = (t >= 0.f) ? t : ALPHA * t;
            float ex = (am[k] > 0) ? __expf(t) : 0.f;
            w[k] = ex;
            psum += ex;
        }
        *(float4*)&wsm[ra*64 + ga*8]     = make_float4(w[0], w[1], w[2], w[3]);
        *(float4*)&wsm[ra*64 + ga*8 + 4] = make_float4(w[4], w[5], w[6], w[7]);
        // ---- stage Wh chunk as jj-pairs: whs_p[p][n] = (Wh[2p][n], Wh[2p+1][n]) ----
        #pragma unroll
        for (int l = 0; l < 32/G; l++) {
            int p = jg + l*G;
            const float* gp = WhB + (size_t)(jc + 2*p) * F + n_s;
            whs_p[p*F + n_s] = pack2(gp[0], gp[F]);
        }
        __syncthreads();
        // ---- acc += w[32][64] @ WhT, pairwise f32x2, conflict-free ----
        #pragma unroll
        for (int jb = 0; jb < 8; jb++) {
            // 4 jj-pairs per jb; weights broadcast from wsm as u64 pairs
            ulonglong2 wrA[4], wrB[4];
            #pragma unroll
            for (int t = 0; t < 4; t++) {
                wrA[t] = *(const ulonglong2*)&wsm[(ty*4 + t)*64 + jb*8];
                wrB[t] = *(const ulonglong2*)&wsm[(ty*4 + t)*64 + jb*8 + 4];
            }
            #pragma unroll
            for (int q = 0; q < 4; q++) {
                #pragma unroll
                for (int u = 0; u < TN; u++) {
                    u64 wv = whs_p[(jb*4 + q)*F + tx + 32*u];
                    #pragma unroll
                    for (int t = 0; t < 4; t++) {
                        u64 wp = (q == 0) ? wrA[t].x : (q == 1) ? wrA[t].y
                               : (q == 2) ? wrB[t].x : wrB[t].y;
                        acc[t][u] = fma2(wp, wv, acc[t][u]);
                    }
                }
            }
        }
        __syncthreads();
    }
    // row sums (8 threads per row)
    #pragma unroll
    for (int o = 4; o; o >>= 1) psum += __shfl_down_sync(0xffffffffu, psum, o, 8);
    if (ga == 0) rowsumS[ra] = psum;
    __syncthreads();
    // normalize + elu + store
    int colOff = h * F;
    #pragma unroll
    for (int t = 0; t < 4; t++) {
        int r = ty*4 + t;
        float inv = 1.f / rowsumS[r];
        float* op = out + ((size_t)b * NA + row0 + r) * outRowStride + colOff;
        #pragma unroll
        for (int u = 0; u < TN; u++) {
            float2 pr = u2f(acc[t][u]);
            float v = (pr.x + pr.y) * inv;
            v = (v > 0.f) ? v : expm1f(v);
            op[tx + 32*u] = v;
        }
    }
}

// ---------------- 11x11 conv, SAME pad, relu, 4 outputs/thread ----------------
template<bool G>
__global__ __launch_bounds__(256) void conv11r(const float* __restrict__ in,
        const int* __restrict__ gidx, const float* __restrict__ wconv,
        const float* __restrict__ bconv, int layer, float* __restrict__ out) {
    __shared__ float tile[42][42];
    __shared__ float ws[121];
    int b = blockIdx.z, ly0 = blockIdx.y * 32, lx0 = blockIdx.x * 32;
    int tid = threadIdx.x;
    int tx = tid & 31, ty = tid >> 5;
    if (tid < 121) ws[tid] = wconv[layer*121 + tid];
    const float* inb = in + (size_t)b * LA * CD;
    const int* gb = gidx + (size_t)b * LA;
    for (int e = tid; e < 42*42; e += 256) {
        int sy = e / 42, sx = e % 42;
        int gy = ly0 + sy - 5, gx = lx0 + sx - 5;
        float val = 0.f;
        if (gy >= 0 && gy < LA && gx >= 0 && gx < CD) {
            if (G) val = in[(size_t)gb[gy]*CD + gx];
            else   val = inb[(size_t)gy*CD + gx];
        }
        tile[sy][sx] = val;
    }
    __syncthreads();
    float bz = bconv[layer];
    float acc[4] = {bz, bz, bz, bz};
    #pragma unroll
    for (int kx = 0; kx < 11; kx++) {
        float v[14];
        #pragma unroll
        for (int r = 0; r < 14; r++) v[r] = tile[ty*4 + r][tx + kx];
        #pragma unroll
        for (int ky = 0; ky < 11; ky++) {
            float wv = ws[ky*11 + kx];
            #pragma unroll
            for (int i = 0; i < 4; i++) acc[i] += v[ky + i] * wv;
        }
    }
    #pragma unroll
    for (int i = 0; i < 4; i++)
        out[(size_t)b*LA*CD + (size_t)(ly0 + ty*4 + i)*CD + lx0 + tx] = fmaxf(acc[i], 0.f);
}

// ---------------- finalize: pools -> lrelu^2 -> dot ---------------------------
__global__ void finalize(const float* __restrict__ part, const float* __restrict__ part2,
                         const float* __restrict__ amask, const float* __restrict__ pmask,
                         const float* __restrict__ pw, const float* __restrict__ pb,
                         float* __restrict__ out) {
    __shared__ float redA[256], redB[256], red[256];
    int b = blockIdx.x, t = threadIdx.x;
    float msA = 0.f, msP = 0.f;
    for (int i = t; i < NA; i += 256) msA += amask[(size_t)b*NA + i];
    for (int i = t; i < LA; i += 256) msP += pmask[(size_t)b*LA + i];
    redA[t] = msA; redB[t] = msP;
    __syncthreads();
    for (int o = 128; o; o >>= 1) {
        if (t < o) { redA[t] += redA[t+o]; redB[t] += redB[t+o]; }
        __syncthreads();
    }
    float v = (t < 128) ? part[b*LT + t] / redA[0] : part2[b*LT + (t - 128)] / redB[0];
    v = (v >= 0.f) ? v : ALPHA * v;
    v = (v >= 0.f) ? v : ALPHA * v;
    red[t] = v * pw[t];
    __syncthreads();
    for (int o = 128; o; o >>= 1) {
        if (t < o) red[t] += red[t + o];
        __syncthreads();
    }
    if (t == 0) out[b] = red[0] + pb[0];
}

// ------------------------------------------------------------------------------
extern "C" void kernel_launch(void* const* d_in, const int* in_sizes, int n_in,
                              void* d_out, int out_size) {
    const int*   atoms      = (const int*)  d_in[0];
    const float* atoms_mask = (const float*)d_in[1];
    const int*   adjacency  = (const int*)  d_in[2];
    const int*   amino      = (const int*)  d_in[3];
    const float* amino_mask = (const float*)d_in[4];
    const float* E_atom     = (const float*)d_in[5];
    const float* E_amino    = (const float*)d_in[6];
    const float* W_gat      = (const float*)d_in[7];
    const float* a_gat      = (const float*)d_in[8];
    const float* W_go       = (const float*)d_in[9];
    const float* a_go       = (const float*)d_in[10];
    const float* W_comp_w   = (const float*)d_in[11];
    const float* W_comp_b   = (const float*)d_in[12];
    const float* conv_w     = (const float*)d_in[13];
    const float* conv_b     = (const float*)d_in[14];
    const float* W_att_w    = (const float*)d_in[15];
    const float* W_att_b    = (const float*)d_in[16];
    const float* pred_w     = (const float*)d_in[17];
    const float* pred_b     = (const float*)d_in[18];
    float* outp = (float*)d_out;

    float *p_Wh, *p_src, *p_dst, *p_multi, *p_Wh2, *p_src2, *p_dst2;
    float *p_x, *p_atoms_vec, *p_pv0, *p_pv1, *p_part, *p_part2;
    cudaGetSymbolAddress((void**)&p_Wh, g_Wh);
    cudaGetSymbolAddress((void**)&p_src, g_src);
    cudaGetSymbolAddress((void**)&p_dst, g_dst);
    cudaGetSymbolAddress((void**)&p_multi, g_multi);
    cudaGetSymbolAddress((void**)&p_Wh2, g_Wh2);
    cudaGetSymbolAddress((void**)&p_src2, g_src2);
    cudaGetSymbolAddress((void**)&p_dst2, g_dst2);
    cudaGetSymbolAddress((void**)&p_x, g_x);
    cudaGetSymbolAddress((void**)&p_atoms_vec, g_atoms_vec);
    cudaGetSymbolAddress((void**)&p_pv0, g_pv0);
    cudaGetSymbolAddress((void**)&p_pv1, g_pv1);
    cudaGetSymbolAddress((void**)&p_part, g_part);
    cudaGetSymbolAddress((void**)&p_part2, g_part2);

    // fork stream + events for the independent protein path (capture-legal).
    // NOTE: never destroyed inside this call — destroying a stream that is part
    // of an active capture invalidates the capture. Created twice total
    // (correctness call + capture call); host-side leak only.
    cudaStream_t s2;
    cudaEvent_t evFork, evJoin;
    cudaStreamCreateWithFlags(&s2, cudaStreamNonBlocking);
    cudaEventCreateWithFlags(&evFork, cudaEventDisableTiming);
    cudaEventCreateWithFlags(&evJoin, cudaEventDisableTiming);

    // zero accumulators (graph-capturable memset nodes)
    cudaMemsetAsync(p_part,  0, B_*LT*sizeof(float));
    cudaMemsetAsync(p_part2, 0, B_*LT*sizeof(float));
    cudaMemsetAsync(p_src,  0, NH*B_*NA*sizeof(float));
    cudaMemsetAsync(p_dst,  0, NH*B_*NA*sizeof(float));
    cudaMemsetAsync(p_src2, 0, B_*NA*sizeof(float));
    cudaMemsetAsync(p_dst2, 0, B_*NA*sizeof(float));

    // -------- fork: protein path on s2 --------
    cudaEventRecord(evFork, 0);
    cudaStreamWaitEvent(s2, evFork, 0);
    conv11r<true ><<<dim3(4,32,B_), 256, 0, s2>>>(E_amino, amino, conv_w, conv_b, 0, p_pv1);
    conv11r<false><<<dim3(4,32,B_), 256, 0, s2>>>(p_pv1, amino, conv_w, conv_b, 1, p_pv0);
    conv11r<false><<<dim3(4,32,B_), 256, 0, s2>>>(p_pv0, amino, conv_w, conv_b, 2, p_pv1);
    sgemmX<true,2,false,false><<<dim3(2,8,B_), 256, 0, s2>>>(
        p_pv1, W_att_w, W_att_b, nullptr, nullptr, nullptr, nullptr, nullptr,
        amino_mask, p_part2,
        LA, LT, LT, (size_t)LA*LT, 0, 0, 1, 0);
    cudaEventRecord(evJoin, s2);

    // -------- atom/GAT path on default stream --------
    // 1. layer-1 GAT projection (gather + fused src/dst dots)
    sgemmX<false,0,true,true><<<dim3(1,4,NH*B_), 256>>>(
        E_atom, W_gat, nullptr, p_Wh, atoms, a_gat, p_src, p_dst, nullptr, nullptr,
        NA, GD, CD, 0, B_, (size_t)CD*GD, B_, (size_t)NA*GD);
    attn2x<GD><<<dim3(NA/32, NH*B_), 256>>>(p_Wh, p_src, p_dst,
        adjacency, p_multi, NH*GD, B_);

    // 2. layer-2 GAT projection (fused src/dst dots, N=128 via atomics)
    sgemmX<false,0,false,true><<<dim3(2,4,B_), 256>>>(
        p_multi, W_go, nullptr, p_Wh2, nullptr, a_go, p_src2, p_dst2, nullptr, nullptr,
        NA, CD, NH*GD, (size_t)NA*NH*GD, 0, 0, 1, (size_t)NA*CD);
    attn2x<CD><<<dim3(NA/32, B_), 256>>>(p_Wh2, p_src2, p_dst2,
        adjacency, p_x, CD, B_);

    // 3. atoms_vec = lrelu(x @ Wc^T + bc);  pool(lrelu(atoms_vec @ Wa^T + ba))
    sgemmX<true,1,false,false><<<dim3(2,4,B_), 256>>>(
        p_x, W_comp_w, W_comp_b, p_atoms_vec, nullptr, nullptr, nullptr, nullptr, nullptr, nullptr,
        NA, LT, CD, (size_t)NA*CD, 0, 0, 1, (size_t)NA*LT);
    sgemmX<true,2,false,false><<<dim3(2,4,B_), 256>>>(
        p_atoms_vec, W_att_w, W_att_b, nullptr, nullptr, nullptr, nullptr, nullptr,
        atoms_mask, p_part,
        NA, LT, LT, (size_t)NA*LT, 0, 0, 1, 0);

    // -------- join + finalize --------
    cudaStreamWaitEvent(0, evJoin, 0);
    finalize<<<B_, 256>>>(p_part, p_part2, atoms_mask, amino_mask, pred_w, pred_b, outp);
}

// round 9
// speedup vs baseline: 2.3177x; 1.0305x over previous
#include <cuda_runtime.h>
#include <math.h>

#define B_  16
#define NA  512
#define LA  1024
#define CD  128
#define GD  64
#define NH  4
#define LT  128
#define ALPHA 0.2f

typedef unsigned long long u64;

static __device__ __forceinline__ u64 fma2(u64 a, u64 b, u64 c) {
    u64 d;
    asm("fma.rn.f32x2 %0, %1, %2, %3;" : "=l"(d) : "l"(a), "l"(b), "l"(c));
    return d;
}
static __device__ __forceinline__ u64 pack2(float lo, float hi) {
    u64 r;
    asm("mov.b64 %0, {%1, %2};" : "=l"(r) : "f"(lo), "f"(hi));
    return r;
}
static __device__ __forceinline__ float2 u2f(u64 v) {
    float2 r;
    asm("mov.b64 {%0, %1}, %2;" : "=f"(r.x), "=f"(r.y) : "l"(v));
    return r;
}

// ---------------- scratch (static device globals; no allocations) -------------
__device__ float g_Wh[NH*B_*NA*GD];
__device__ float g_src[NH*B_*NA];
__device__ float g_dst[NH*B_*NA];
__device__ float g_multi[B_*NA*NH*GD];
__device__ float g_Wh2[B_*NA*CD];
__device__ float g_src2[B_*NA];
__device__ float g_dst2[B_*NA];
__device__ float g_x[B_*NA*CD];
__device__ float g_atoms_vec[B_*NA*LT];
__device__ float g_pv0[B_*LA*CD];
__device__ float g_pv1[B_*LA*CD];
__device__ float g_part[B_*LT];
__device__ float g_part2[B_*LT];

// ---------------- SGEMM with f32x2 K-paired inner loop ------------------------
// BM=128 BN=64 BK=16, 256 threads, 8x4 microtile; column map n = tx + 16*j.
// EPI: 0 none, 1 bias+leaky_relu (store), 2 bias+leaky_relu + masked column-sum
//      into part[] (NO store).  GATHER: A rows via gidx.  SRCDST: atomicAdd
//      partial src/dst dot products with avec (supports N > BN).
// Register budget tuned for 2 CTAs/SM: bQ loaded per-j inside the q loop.
template<bool BT, int EPI, bool GATHER, bool SRCDST>
__global__ __launch_bounds__(256, 2) void sgemmX(
        const float* __restrict__ A, const float* __restrict__ Bm,
        const float* __restrict__ bias, float* __restrict__ C,
        const int* __restrict__ gidx,
        const float* __restrict__ avec, float* __restrict__ srcO, float* __restrict__ dstO,
        const float* __restrict__ mask, float* __restrict__ part,
        int M, int N, int K,
        size_t aBat, int aMod, size_t bBat, int bDiv, size_t cBat) {
    __shared__ __align__(16) float As_t[128*16];
    __shared__ __align__(16) float Bs_t[64*20];
    int z = blockIdx.z;
    int zb = aMod ? (z % aMod) : z;
    if (!GATHER) A += (size_t)zb * aBat;
    Bm += (size_t)(bDiv ? (z / bDiv) : z) * bBat;
    C  += (size_t)z * cBat;
    int bn = blockIdx.x * 64, bm = blockIdx.y * 128;
    int tid = threadIdx.x;
    int tx = tid & 15, ty = tid >> 4;
    u64 acc[8][4] = {};
    for (int k0 = 0; k0 < K; k0 += 16) {
        #pragma unroll
        for (int l = 0; l < 2; l++) {
            int e = tid + l*256;
            int m = e >> 2, k4 = (e & 3) * 4;
            const float* sp;
            if (GATHER) {
                int row = gidx[(size_t)zb * M + bm + m];
                sp = &A[(size_t)row * K + k0 + k4];
            } else {
                sp = &A[(size_t)(bm + m) * K + k0 + k4];
            }
            *(float4*)&As_t[m*16 + k4] = *(const float4*)sp;
        }
        if (BT) {
            int n = tid >> 2, k4 = (tid & 3) * 4;
            *(float4*)&Bs_t[n*20 + k4] = *(const float4*)&Bm[(size_t)(bn + n)*K + k0 + k4];
        } else {
            int k = tid >> 4, n4 = (tid & 15) * 4;
            float4 v = *(const float4*)&Bm[(size_t)(k0 + k)*N + bn + n4];
            Bs_t[(n4+0)*20 + k] = v.x;
            Bs_t[(n4+1)*20 + k] = v.y;
            Bs_t[(n4+2)*20 + k] = v.z;
            Bs_t[(n4+3)*20 + k] = v.w;
        }
        __syncthreads();
        #pragma unroll
        for (int q = 0; q < 4; q++) {
            ulonglong2 aQ[8];
            #pragma unroll
            for (int i = 0; i < 8; i++)
                aQ[i] = *(const ulonglong2*)&As_t[(ty*8 + i)*16 + q*4];
            #pragma unroll
            for (int j = 0; j < 4; j++) {
                ulonglong2 bq = *(const ulonglong2*)&Bs_t[(tx + 16*j)*20 + q*4];
                #pragma unroll
                for (int i = 0; i < 8; i++) {
                    acc[i][j] = fma2(aQ[i].x, bq.x, acc[i][j]);
                    acc[i][j] = fma2(aQ[i].y, bq.y, acc[i][j]);
                }
            }
        }
        __syncthreads();
    }
    // collapse pairs
    float vv[8][4];
    #pragma unroll
    for (int i = 0; i < 8; i++)
        #pragma unroll
        for (int j = 0; j < 4; j++) {
            float2 p = u2f(acc[i][j]);
            float v = p.x + p.y;
            if (EPI >= 1) {
                v += bias[bn + tx + 16*j];
                v = (v >= 0.f) ? v : ALPHA * v;
            }
            vv[i][j] = v;
        }
    if (EPI == 2) {
        const float* maskB = mask + (size_t)z * M;
        float cs[4] = {};
        #pragma unroll
        for (int i = 0; i < 8; i++) {
            float mk = maskB[bm + ty*8 + i];
            #pragma unroll
            for (int j = 0; j < 4; j++) cs[j] += vv[i][j] * mk;
        }
        float* sred = As_t;  // reuse: [16][64]
        #pragma unroll
        for (int j = 0; j < 4; j++) sred[ty*64 + tx + 16*j] = cs[j];
        __syncthreads();
        if (tid < 64) {
            float s = 0.f;
            #pragma unroll
            for (int t = 0; t < 16; t++) s += sred[t*64 + tid];
            atomicAdd(&part[(size_t)z * LT + bn + tid], s);
        }
        return;
    }
    #pragma unroll
    for (int i = 0; i < 8; i++) {
        int m = bm + ty*8 + i;
        #pragma unroll
        for (int j = 0; j < 4; j++)
            C[(size_t)m * N + bn + tx + 16*j] = vv[i][j];
    }
    if (SRCDST) {
        const float* av = avec + (size_t)(bDiv ? (z / bDiv) : 0) * 2 * N;
        float a0[4], a1[4];
        #pragma unroll
        for (int j = 0; j < 4; j++) {
            a0[j] = av[bn + tx + 16*j];
            a1[j] = av[N + bn + tx + 16*j];
        }
        #pragma unroll
        for (int i = 0; i < 8; i++) {
            float s = 0.f, d = 0.f;
            #pragma unroll
            for (int j = 0; j < 4; j++) {
                s += vv[i][j] * a0[j];
                d += vv[i][j] * a1[j];
            }
            #pragma unroll
            for (int o = 8; o; o >>= 1) {
                s += __shfl_xor_sync(0xffffffffu, s, o);
                d += __shfl_xor_sync(0xffffffffu, d, o);
            }
            if (tx == 0) {
                int m = bm + ty*8 + i;
                atomicAdd(&srcO[(size_t)z * M + m], s);
                atomicAdd(&dstO[(size_t)z * M + m], d);
            }
        }
    }
}

// ---------------- fused GAT attention, f32x2 pair-major (conflict-free) -------
// 32 rows/block, 256 threads.  Column map: n = tx + 32*u.
template<int F>
__global__ __launch_bounds__(256, 2) void attn2x(
        const float* __restrict__ Wh, const float* __restrict__ src,
        const float* __restrict__ dst, const int* __restrict__ adj,
        float* __restrict__ out, int outRowStride, int nb) {
    constexpr int TN = F / 32;       // 2 or 4
    constexpr int G = 256 / F;       // staging groups
    __shared__ __align__(16) float wsm[32*64];
    __shared__ __align__(16) u64 whs_p[32 * F];   // [pair jj/2][n]
    __shared__ float rowsumS[32];
    int hb = blockIdx.y;
    int b = hb % nb, h = hb / nb;
    const float* WhB  = Wh  + (size_t)hb * NA * F;
    const float* srcB = src + (size_t)hb * NA;
    const float* dstB = dst + (size_t)hb * NA;
    const int*   adjB = adj + (size_t)b * NA * NA;
    int row0 = blockIdx.x * 32;
    int tid = threadIdx.x;
    int ra = tid >> 3, ga = tid & 7;
    float srow = srcB[row0 + ra];
    const int* arow = adjB + (size_t)(row0 + ra) * NA + ga * 8;
    int tx = tid & 31, ty = tid >> 5;
    int n_s = tid % F, jg = tid / F;
    u64 acc[4][TN] = {};
    float psum = 0.f;

    for (int jc = 0; jc < NA; jc += 64) {
        // ---- phase A: masked exp(leaky(src+dst)) -> wsm ----
        const int4* ap = (const int4*)(arow + jc);
        int4 A0 = ap[0], A1 = ap[1];
        const float4* dp = (const float4*)(dstB + jc + ga*8);
        float4 d0 = dp[0], d1 = dp[1];
        int   am[8] = {A0.x,A0.y,A0.z,A0.w,A1.x,A1.y,A1.z,A1.w};
        float dv[8] = {d0.x,d0.y,d0.z,d0.w,d1.x,d1.y,d1.z,d1.w};
        float w[8];
        #pragma unroll
        for (int k = 0; k < 8; k++) {
            float t = srow + dv[k];
            t = (t >= 0.f) ? t : ALPHA * t;
            float ex = (am[k] > 0) ? __expf(t) : 0.f;
            w[k] = ex;
            psum += ex;
        }
        *(float4*)&wsm[ra*64 + ga*8]     = make_float4(w[0], w[1], w[2], w[3]);
        *(float4*)&wsm[ra*64 + ga*8 + 4] = make_float4(w[4], w[5], w[6], w[7]);
        // ---- stage Wh chunk as jj-pairs: whs_p[p][n] = (Wh[2p][n], Wh[2p+1][n]) ----
        #pragma unroll
        for (int l = 0; l < 32/G; l++) {
            int p = jg + l*G;
            const float* gp = WhB + (size_t)(jc + 2*p) * F + n_s;
            whs_p[p*F + n_s] = pack2(gp[0], gp[F]);
        }
        __syncthreads();
        // ---- acc += w[32][64] @ WhT, pairwise f32x2, conflict-free ----
        #pragma unroll
        for (int jb = 0; jb < 8; jb++) {
            // 4 jj-pairs per jb; weights broadcast from wsm as u64 pairs
            ulonglong2 wrA[4], wrB[4];
            #pragma unroll
            for (int t = 0; t < 4; t++) {
                wrA[t] = *(const ulonglong2*)&wsm[(ty*4 + t)*64 + jb*8];
                wrB[t] = *(const ulonglong2*)&wsm[(ty*4 + t)*64 + jb*8 + 4];
            }
            #pragma unroll
            for (int q = 0; q < 4; q++) {
                #pragma unroll
                for (int u = 0; u < TN; u++) {
                    u64 wv = whs_p[(jb*4 + q)*F + tx + 32*u];
                    #pragma unroll
                    for (int t = 0; t < 4; t++) {
                        u64 wp = (q == 0) ? wrA[t].x : (q == 1) ? wrA[t].y
                               : (q == 2) ? wrB[t].x : wrB[t].y;
                        acc[t][u] = fma2(wp, wv, acc[t][u]);
                    }
                }
            }
        }
        __syncthreads();
    }
    // row sums (8 threads per row)
    #pragma unroll
    for (int o = 4; o; o >>= 1) psum += __shfl_down_sync(0xffffffffu, psum, o, 8);
    if (ga == 0) rowsumS[ra] = psum;
    __syncthreads();
    // normalize + elu + store
    int colOff = h * F;
    #pragma unroll
    for (int t = 0; t < 4; t++) {
        int r = ty*4 + t;
        float inv = 1.f / rowsumS[r];
        float* op = out + ((size_t)b * NA + row0 + r) * outRowStride + colOff;
        #pragma unroll
        for (int u = 0; u < TN; u++) {
            float2 pr = u2f(acc[t][u]);
            float v = (pr.x + pr.y) * inv;
            v = (v > 0.f) ? v : expm1f(v);
            op[tx + 32*u] = v;
        }
    }
}

// ---------------- 11x11 conv, SAME pad, relu, 4 outputs/thread ----------------
template<bool G>
__global__ __launch_bounds__(256) void conv11r(const float* __restrict__ in,
        const int* __restrict__ gidx, const float* __restrict__ wconv,
        const float* __restrict__ bconv, int layer, float* __restrict__ out) {
    __shared__ float tile[42][42];
    __shared__ float ws[121];
    int b = blockIdx.z, ly0 = blockIdx.y * 32, lx0 = blockIdx.x * 32;
    int tid = threadIdx.x;
    int tx = tid & 31, ty = tid >> 5;
    if (tid < 121) ws[tid] = wconv[layer*121 + tid];
    const float* inb = in + (size_t)b * LA * CD;
    const int* gb = gidx + (size_t)b * LA;
    for (int e = tid; e < 42*42; e += 256) {
        int sy = e / 42, sx = e % 42;
        int gy = ly0 + sy - 5, gx = lx0 + sx - 5;
        float val = 0.f;
        if (gy >= 0 && gy < LA && gx >= 0 && gx < CD) {
            if (G) val = in[(size_t)gb[gy]*CD + gx];
            else   val = inb[(size_t)gy*CD + gx];
        }
        tile[sy][sx] = val;
    }
    __syncthreads();
    float bz = bconv[layer];
    float acc[4] = {bz, bz, bz, bz};
    #pragma unroll
    for (int kx = 0; kx < 11; kx++) {
        float v[14];
        #pragma unroll
        for (int r = 0; r < 14; r++) v[r] = tile[ty*4 + r][tx + kx];
        #pragma unroll
        for (int ky = 0; ky < 11; ky++) {
            float wv = ws[ky*11 + kx];
            #pragma unroll
            for (int i = 0; i < 4; i++) acc[i] += v[ky + i] * wv;
        }
    }
    #pragma unroll
    for (int i = 0; i < 4; i++)
        out[(size_t)b*LA*CD + (size_t)(ly0 + ty*4 + i)*CD + lx0 + tx] = fmaxf(acc[i], 0.f);
}

// ---------------- finalize: pools -> lrelu^2 -> dot ---------------------------
__global__ void finalize(const float* __restrict__ part, const float* __restrict__ part2,
                         const float* __restrict__ amask, const float* __restrict__ pmask,
                         const float* __restrict__ pw, const float* __restrict__ pb,
                         float* __restrict__ out) {
    __shared__ float redA[256], redB[256], red[256];
    int b = blockIdx.x, t = threadIdx.x;
    float msA = 0.f, msP = 0.f;
    for (int i = t; i < NA; i += 256) msA += amask[(size_t)b*NA + i];
    for (int i = t; i < LA; i += 256) msP += pmask[(size_t)b*LA + i];
    redA[t] = msA; redB[t] = msP;
    __syncthreads();
    for (int o = 128; o; o >>= 1) {
        if (t < o) { redA[t] += redA[t+o]; redB[t] += redB[t+o]; }
        __syncthreads();
    }
    float v = (t < 128) ? part[b*LT + t] / redA[0] : part2[b*LT + (t - 128)] / redB[0];
    v = (v >= 0.f) ? v : ALPHA * v;
    v = (v >= 0.f) ? v : ALPHA * v;
    red[t] = v * pw[t];
    __syncthreads();
    for (int o = 128; o; o >>= 1) {
        if (t < o) red[t] += red[t + o];
        __syncthreads();
    }
    if (t == 0) out[b] = red[0] + pb[0];
}

// ------------------------------------------------------------------------------
extern "C" void kernel_launch(void* const* d_in, const int* in_sizes, int n_in,
                              void* d_out, int out_size) {
    const int*   atoms      = (const int*)  d_in[0];
    const float* atoms_mask = (const float*)d_in[1];
    const int*   adjacency  = (const int*)  d_in[2];
    const int*   amino      = (const int*)  d_in[3];
    const float* amino_mask = (const float*)d_in[4];
    const float* E_atom     = (const float*)d_in[5];
    const float* E_amino    = (const float*)d_in[6];
    const float* W_gat      = (const float*)d_in[7];
    const float* a_gat      = (const float*)d_in[8];
    const float* W_go       = (const float*)d_in[9];
    const float* a_go       = (const float*)d_in[10];
    const float* W_comp_w   = (const float*)d_in[11];
    const float* W_comp_b   = (const float*)d_in[12];
    const float* conv_w     = (const float*)d_in[13];
    const float* conv_b     = (const float*)d_in[14];
    const float* W_att_w    = (const float*)d_in[15];
    const float* W_att_b    = (const float*)d_in[16];
    const float* pred_w     = (const float*)d_in[17];
    const float* pred_b     = (const float*)d_in[18];
    float* outp = (float*)d_out;

    float *p_Wh, *p_src, *p_dst, *p_multi, *p_Wh2, *p_src2, *p_dst2;
    float *p_x, *p_atoms_vec, *p_pv0, *p_pv1, *p_part, *p_part2;
    cudaGetSymbolAddress((void**)&p_Wh, g_Wh);
    cudaGetSymbolAddress((void**)&p_src, g_src);
    cudaGetSymbolAddress((void**)&p_dst, g_dst);
    cudaGetSymbolAddress((void**)&p_multi, g_multi);
    cudaGetSymbolAddress((void**)&p_Wh2, g_Wh2);
    cudaGetSymbolAddress((void**)&p_src2, g_src2);
    cudaGetSymbolAddress((void**)&p_dst2, g_dst2);
    cudaGetSymbolAddress((void**)&p_x, g_x);
    cudaGetSymbolAddress((void**)&p_atoms_vec, g_atoms_vec);
    cudaGetSymbolAddress((void**)&p_pv0, g_pv0);
    cudaGetSymbolAddress((void**)&p_pv1, g_pv1);
    cudaGetSymbolAddress((void**)&p_part, g_part);
    cudaGetSymbolAddress((void**)&p_part2, g_part2);

    // fork stream + events for the independent protein path (capture-legal).
    // NOTE: never destroyed inside this call — destroying a stream that is part
    // of an active capture invalidates the capture. Created twice total
    // (correctness call + capture call); host-side leak only.
    cudaStream_t s2;
    cudaEvent_t evFork, evJoin;
    cudaStreamCreateWithFlags(&s2, cudaStreamNonBlocking);
    cudaEventCreateWithFlags(&evFork, cudaEventDisableTiming);
    cudaEventCreateWithFlags(&evJoin, cudaEventDisableTiming);

    // zero accumulators (graph-capturable memset nodes)
    cudaMemsetAsync(p_part,  0, B_*LT*sizeof(float));
    cudaMemsetAsync(p_part2, 0, B_*LT*sizeof(float));
    cudaMemsetAsync(p_src,  0, NH*B_*NA*sizeof(float));
    cudaMemsetAsync(p_dst,  0, NH*B_*NA*sizeof(float));
    cudaMemsetAsync(p_src2, 0, B_*NA*sizeof(float));
    cudaMemsetAsync(p_dst2, 0, B_*NA*sizeof(float));

    // -------- fork: protein path on s2 --------
    cudaEventRecord(evFork, 0);
    cudaStreamWaitEvent(s2, evFork, 0);
    conv11r<true ><<<dim3(4,32,B_), 256, 0, s2>>>(E_amino, amino, conv_w, conv_b, 0, p_pv1);
    conv11r<false><<<dim3(4,32,B_), 256, 0, s2>>>(p_pv1, amino, conv_w, conv_b, 1, p_pv0);
    conv11r<false><<<dim3(4,32,B_), 256, 0, s2>>>(p_pv0, amino, conv_w, conv_b, 2, p_pv1);
    sgemmX<true,2,false,false><<<dim3(2,8,B_), 256, 0, s2>>>(
        p_pv1, W_att_w, W_att_b, nullptr, nullptr, nullptr, nullptr, nullptr,
        amino_mask, p_part2,
        LA, LT, LT, (size_t)LA*LT, 0, 0, 1, 0);
    cudaEventRecord(evJoin, s2);

    // -------- atom/GAT path on default stream --------
    // 1. layer-1 GAT projection (gather + fused src/dst dots; head = z/B_)
    sgemmX<false,0,true,true><<<dim3(1,4,NH*B_), 256>>>(
        E_atom, W_gat, nullptr, p_Wh, atoms, a_gat, p_src, p_dst, nullptr, nullptr,
        NA, GD, CD, 0, B_, (size_t)CD*GD, B_, (size_t)NA*GD);
    attn2x<GD><<<dim3(NA/32, NH*B_), 256>>>(p_Wh, p_src, p_dst,
        adjacency, p_multi, NH*GD, B_);

    // 2. layer-2 GAT projection (fused src/dst dots; bDiv=B_ so avec head = 0,
    //    bBat=0 keeps Bm unoffset — fixes OOB read of a_go for z>0)
    sgemmX<false,0,false,true><<<dim3(2,4,B_), 256>>>(
        p_multi, W_go, nullptr, p_Wh2, nullptr, a_go, p_src2, p_dst2, nullptr, nullptr,
        NA, CD, NH*GD, (size_t)NA*NH*GD, 0, 0, B_, (size_t)NA*CD);
    attn2x<CD><<<dim3(NA/32, B_), 256>>>(p_Wh2, p_src2, p_dst2,
        adjacency, p_x, CD, B_);

    // 3. atoms_vec = lrelu(x @ Wc^T + bc);  pool(lrelu(atoms_vec @ Wa^T + ba))
    sgemmX<true,1,false,false><<<dim3(2,4,B_), 256>>>(
        p_x, W_comp_w, W_comp_b, p_atoms_vec, nullptr, nullptr, nullptr, nullptr, nullptr, nullptr,
        NA, LT, CD, (size_t)NA*CD, 0, 0, 1, (size_t)NA*LT);
    sgemmX<true,2,false,false><<<dim3(2,4,B_), 256>>>(
        p_atoms_vec, W_att_w, W_att_b, nullptr, nullptr, nullptr, nullptr, nullptr,
        atoms_mask, p_part,
        NA, LT, LT, (size_t)NA*LT, 0, 0, 1, 0);

    // -------- join + finalize --------
    cudaStreamWaitEvent(0, evJoin, 0);
    finalize<<<B_, 256>>>(p_part, p_part2, atoms_mask, amino_mask, pred_w, pred_b, outp);
}

// round 10
// speedup vs baseline: 2.3527x; 1.0151x over previous
#include <cuda_runtime.h>
#include <math.h>

#define B_  16
#define NA  512
#define LA  1024
#define CD  128
#define GD  64
#define NH  4
#define LT  128
#define ALPHA 0.2f

typedef unsigned long long u64;

static __device__ __forceinline__ u64 fma2(u64 a, u64 b, u64 c) {
    u64 d;
    asm("fma.rn.f32x2 %0, %1, %2, %3;" : "=l"(d) : "l"(a), "l"(b), "l"(c));
    return d;
}
static __device__ __forceinline__ u64 pack2(float lo, float hi) {
    u64 r;
    asm("mov.b64 %0, {%1, %2};" : "=l"(r) : "f"(lo), "f"(hi));
    return r;
}
static __device__ __forceinline__ float2 u2f(u64 v) {
    float2 r;
    asm("mov.b64 {%0, %1}, %2;" : "=f"(r.x), "=f"(r.y) : "l"(v));
    return r;
}

// ---------------- scratch (static device globals; no allocations) -------------
__device__ float g_Wh[NH*B_*NA*GD];
__device__ float g_src[NH*B_*NA];
__device__ float g_dst[NH*B_*NA];
__device__ float g_multi[B_*NA*NH*GD];
__device__ float g_Wh2[B_*NA*CD];
__device__ float g_src2[B_*NA];
__device__ float g_dst2[B_*NA];
__device__ float g_x[B_*NA*CD];
__device__ float g_atoms_vec[B_*NA*LT];
__device__ float g_pv0[B_*LA*CD];
__device__ float g_pv1[B_*LA*CD];
__device__ float g_part[B_*LT];
__device__ float g_part2[B_*LT];

// ---------------- SGEMM with f32x2 K-paired inner loop ------------------------
// BM=128 BN=64 BK=16, 256 threads, 8x4 microtile; column map n = tx + 16*j.
template<bool BT, int EPI, bool GATHER, bool SRCDST>
__global__ __launch_bounds__(256, 2) void sgemmX(
        const float* __restrict__ A, const float* __restrict__ Bm,
        const float* __restrict__ bias, float* __restrict__ C,
        const int* __restrict__ gidx,
        const float* __restrict__ avec, float* __restrict__ srcO, float* __restrict__ dstO,
        const float* __restrict__ mask, float* __restrict__ part,
        int M, int N, int K,
        size_t aBat, int aMod, size_t bBat, int bDiv, size_t cBat) {
    __shared__ __align__(16) float As_t[128*16];
    __shared__ __align__(16) float Bs_t[64*20];
    int z = blockIdx.z;
    int zb = aMod ? (z % aMod) : z;
    if (!GATHER) A += (size_t)zb * aBat;
    Bm += (size_t)(bDiv ? (z / bDiv) : z) * bBat;
    C  += (size_t)z * cBat;
    int bn = blockIdx.x * 64, bm = blockIdx.y * 128;
    int tid = threadIdx.x;
    int tx = tid & 15, ty = tid >> 4;
    u64 acc[8][4] = {};
    for (int k0 = 0; k0 < K; k0 += 16) {
        #pragma unroll
        for (int l = 0; l < 2; l++) {
            int e = tid + l*256;
            int m = e >> 2, k4 = (e & 3) * 4;
            const float* sp;
            if (GATHER) {
                int row = gidx[(size_t)zb * M + bm + m];
                sp = &A[(size_t)row * K + k0 + k4];
            } else {
                sp = &A[(size_t)(bm + m) * K + k0 + k4];
            }
            *(float4*)&As_t[m*16 + k4] = *(const float4*)sp;
        }
        if (BT) {
            int n = tid >> 2, k4 = (tid & 3) * 4;
            *(float4*)&Bs_t[n*20 + k4] = *(const float4*)&Bm[(size_t)(bn + n)*K + k0 + k4];
        } else {
            int k = tid >> 4, n4 = (tid & 15) * 4;
            float4 v = *(const float4*)&Bm[(size_t)(k0 + k)*N + bn + n4];
            Bs_t[(n4+0)*20 + k] = v.x;
            Bs_t[(n4+1)*20 + k] = v.y;
            Bs_t[(n4+2)*20 + k] = v.z;
            Bs_t[(n4+3)*20 + k] = v.w;
        }
        __syncthreads();
        #pragma unroll
        for (int q = 0; q < 4; q++) {
            ulonglong2 aQ[8];
            #pragma unroll
            for (int i = 0; i < 8; i++)
                aQ[i] = *(const ulonglong2*)&As_t[(ty*8 + i)*16 + q*4];
            #pragma unroll
            for (int j = 0; j < 4; j++) {
                ulonglong2 bq = *(const ulonglong2*)&Bs_t[(tx + 16*j)*20 + q*4];
                #pragma unroll
                for (int i = 0; i < 8; i++) {
                    acc[i][j] = fma2(aQ[i].x, bq.x, acc[i][j]);
                    acc[i][j] = fma2(aQ[i].y, bq.y, acc[i][j]);
                }
            }
        }
        __syncthreads();
    }
    float vv[8][4];
    #pragma unroll
    for (int i = 0; i < 8; i++)
        #pragma unroll
        for (int j = 0; j < 4; j++) {
            float2 p = u2f(acc[i][j]);
            float v = p.x + p.y;
            if (EPI >= 1) {
                v += bias[bn + tx + 16*j];
                v = (v >= 0.f) ? v : ALPHA * v;
            }
            vv[i][j] = v;
        }
    if (EPI == 2) {
        const float* maskB = mask + (size_t)z * M;
        float cs[4] = {};
        #pragma unroll
        for (int i = 0; i < 8; i++) {
            float mk = maskB[bm + ty*8 + i];
            #pragma unroll
            for (int j = 0; j < 4; j++) cs[j] += vv[i][j] * mk;
        }
        float* sred = As_t;  // reuse: [16][64]
        #pragma unroll
        for (int j = 0; j < 4; j++) sred[ty*64 + tx + 16*j] = cs[j];
        __syncthreads();
        if (tid < 64) {
            float s = 0.f;
            #pragma unroll
            for (int t = 0; t < 16; t++) s += sred[t*64 + tid];
            atomicAdd(&part[(size_t)z * LT + bn + tid], s);
        }
        return;
    }
    #pragma unroll
    for (int i = 0; i < 8; i++) {
        int m = bm + ty*8 + i;
        #pragma unroll
        for (int j = 0; j < 4; j++)
            C[(size_t)m * N + bn + tx + 16*j] = vv[i][j];
    }
    if (SRCDST) {
        const float* av = avec + (size_t)(bDiv ? (z / bDiv) : 0) * 2 * N;
        float a0[4], a1[4];
        #pragma unroll
        for (int j = 0; j < 4; j++) {
            a0[j] = av[bn + tx + 16*j];
            a1[j] = av[N + bn + tx + 16*j];
        }
        #pragma unroll
        for (int i = 0; i < 8; i++) {
            float s = 0.f, d = 0.f;
            #pragma unroll
            for (int j = 0; j < 4; j++) {
                s += vv[i][j] * a0[j];
                d += vv[i][j] * a1[j];
            }
            #pragma unroll
            for (int o = 8; o; o >>= 1) {
                s += __shfl_xor_sync(0xffffffffu, s, o);
                d += __shfl_xor_sync(0xffffffffu, d, o);
            }
            if (tx == 0) {
                int m = bm + ty*8 + i;
                atomicAdd(&srcO[(size_t)z * M + m], s);
                atomicAdd(&dstO[(size_t)z * M + m], d);
            }
        }
    }
}

// ---------------- fused GAT attention: 64-row tiles, TM=8, f32x2 pairs --------
// grid: (NA/64, nb*heads, F/64). Each block computes 64 rows x 64 output cols
// (half = blockIdx.z). 256 threads = 8 warps x 8 rows each. Phase A (exp
// weights) is recomputed per half (cheap); aggregation is f32x2 pair-major.
template<int F>
__global__ __launch_bounds__(256, 2) void attn64(
        const float* __restrict__ Wh, const float* __restrict__ src,
        const float* __restrict__ dst, const int* __restrict__ adj,
        float* __restrict__ out, int outRowStride, int nb) {
    __shared__ __align__(16) float wsm[64*64];
    __shared__ __align__(16) u64 whs_p[32*64];   // [jj-pair][n within half]
    __shared__ float rowsumS[64];
    int hb = blockIdx.y;
    int b = hb % nb, h = hb / nb;
    int half = blockIdx.z;
    const float* WhB  = Wh  + (size_t)hb * NA * F + half*64;
    const float* srcB = src + (size_t)hb * NA;
    const float* dstB = dst + (size_t)hb * NA;
    const int*   adjB = adj + (size_t)b * NA * NA;
    int row0 = blockIdx.x * 64;
    int tid = threadIdx.x;
    // phase A: 4 threads per row, 16 cells each
    int ra = tid >> 2, ga = tid & 3;
    float srow = srcB[row0 + ra];
    const int* arow = adjB + (size_t)(row0 + ra) * NA + ga * 16;
    // phase B: 8 warps x 8 rows; cols tx, tx+32
    int tx = tid & 31, ty = tid >> 5;
    // staging: 4 groups x 64 cols
    int n_s = tid & 63, jg = tid >> 6;
    u64 acc[8][2] = {};
    float psum = 0.f;

    for (int jc = 0; jc < NA; jc += 64) {
        // ---- phase A: masked exp(leaky(src+dst)) -> wsm[64][64] ----
        const int4* ap = (const int4*)(arow + jc);
        const float4* dp = (const float4*)(dstB + jc + ga*16);
        #pragma unroll
        for (int v = 0; v < 4; v++) {
            int4 a4 = ap[v];
            float4 d4 = dp[v];
            int   am[4] = {a4.x, a4.y, a4.z, a4.w};
            float dv[4] = {d4.x, d4.y, d4.z, d4.w};
            float w[4];
            #pragma unroll
            for (int k = 0; k < 4; k++) {
                float t = srow + dv[k];
                t = (t >= 0.f) ? t : ALPHA * t;
                float ex = (am[k] > 0) ? __expf(t) : 0.f;
                w[k] = ex;
                psum += ex;
            }
            *(float4*)&wsm[ra*64 + ga*16 + v*4] = make_float4(w[0], w[1], w[2], w[3]);
        }
        // ---- stage Wh half-chunk as jj-pairs: whs_p[p][n] ----
        #pragma unroll
        for (int l = 0; l < 8; l++) {
            int p = jg + l*4;
            const float* gp = WhB + (size_t)(jc + 2*p) * F + n_s;
            whs_p[p*64 + n_s] = pack2(gp[0], gp[F]);
        }
        __syncthreads();
        // ---- acc += w[64][64] @ WhT, pairwise f32x2 ----
        #pragma unroll
        for (int jb = 0; jb < 16; jb++) {       // 4 jj = 2 pairs per jb
            ulonglong2 wr[8];
            #pragma unroll
            for (int t = 0; t < 8; t++)
                wr[t] = *(const ulonglong2*)&wsm[(ty*8 + t)*64 + jb*4];
            #pragma unroll
            for (int q = 0; q < 2; q++) {
                #pragma unroll
                for (int u = 0; u < 2; u++) {
                    u64 wv = whs_p[(jb*2 + q)*64 + tx + 32*u];
                    #pragma unroll
                    for (int t = 0; t < 8; t++)
                        acc[t][u] = fma2(q == 0 ? wr[t].x : wr[t].y, wv, acc[t][u]);
                }
            }
        }
        __syncthreads();
    }
    // row sums (4 threads per row, consecutive lanes)
    #pragma unroll
    for (int o = 2; o; o >>= 1) psum += __shfl_down_sync(0xffffffffu, psum, o, 4);
    if (ga == 0) rowsumS[ra] = psum;
    __syncthreads();
    // normalize + elu + store
    int colOff = h * F + half * 64;
    #pragma unroll
    for (int t = 0; t < 8; t++) {
        int r = ty*8 + t;
        float inv = 1.f / rowsumS[r];
        float* op = out + ((size_t)b * NA + row0 + r) * outRowStride + colOff;
        #pragma unroll
        for (int u = 0; u < 2; u++) {
            float2 pr = u2f(acc[t][u]);
            float v = (pr.x + pr.y) * inv;
            v = (v > 0.f) ? v : expm1f(v);
            op[tx + 32*u] = v;
        }
    }
}

// ---------------- 11x11 conv, SAME pad, relu, 4 outputs/thread ----------------
template<bool G>
__global__ __launch_bounds__(256) void conv11r(const float* __restrict__ in,
        const int* __restrict__ gidx, const float* __restrict__ wconv,
        const float* __restrict__ bconv, int layer, float* __restrict__ out) {
    __shared__ float tile[42][42];
    __shared__ float ws[121];
    int b = blockIdx.z, ly0 = blockIdx.y * 32, lx0 = blockIdx.x * 32;
    int tid = threadIdx.x;
    int tx = tid & 31, ty = tid >> 5;
    if (tid < 121) ws[tid] = wconv[layer*121 + tid];
    const float* inb = in + (size_t)b * LA * CD;
    const int* gb = gidx + (size_t)b * LA;
    for (int e = tid; e < 42*42; e += 256) {
        int sy = e / 42, sx = e % 42;
        int gy = ly0 + sy - 5, gx = lx0 + sx - 5;
        float val = 0.f;
        if (gy >= 0 && gy < LA && gx >= 0 && gx < CD) {
            if (G) val = in[(size_t)gb[gy]*CD + gx];
            else   val = inb[(size_t)gy*CD + gx];
        }
        tile[sy][sx] = val;
    }
    __syncthreads();
    float bz = bconv[layer];
    float acc[4] = {bz, bz, bz, bz};
    #pragma unroll
    for (int kx = 0; kx < 11; kx++) {
        float v[14];
        #pragma unroll
        for (int r = 0; r < 14; r++) v[r] = tile[ty*4 + r][tx + kx];
        #pragma unroll
        for (int ky = 0; ky < 11; ky++) {
            float wv = ws[ky*11 + kx];
            #pragma unroll
            for (int i = 0; i < 4; i++) acc[i] += v[ky + i] * wv;
        }
    }
    #pragma unroll
    for (int i = 0; i < 4; i++)
        out[(size_t)b*LA*CD + (size_t)(ly0 + ty*4 + i)*CD + lx0 + tx] = fmaxf(acc[i], 0.f);
}

// ---------------- finalize: pools -> lrelu^2 -> dot ---------------------------
__global__ void finalize(const float* __restrict__ part, const float* __restrict__ part2,
                         const float* __restrict__ amask, const float* __restrict__ pmask,
                         const float* __restrict__ pw, const float* __restrict__ pb,
                         float* __restrict__ out) {
    __shared__ float redA[256], redB[256], red[256];
    int b = blockIdx.x, t = threadIdx.x;
    float msA = 0.f, msP = 0.f;
    for (int i = t; i < NA; i += 256) msA += amask[(size_t)b*NA + i];
    for (int i = t; i < LA; i += 256) msP += pmask[(size_t)b*LA + i];
    redA[t] = msA; redB[t] = msP;
    __syncthreads();
    for (int o = 128; o; o >>= 1) {
        if (t < o) { redA[t] += redA[t+o]; redB[t] += redB[t+o]; }
        __syncthreads();
    }
    float v = (t < 128) ? part[b*LT + t] / redA[0] : part2[b*LT + (t - 128)] / redB[0];
    v = (v >= 0.f) ? v : ALPHA * v;
    v = (v >= 0.f) ? v : ALPHA * v;
    red[t] = v * pw[t];
    __syncthreads();
    for (int o = 128; o; o >>= 1) {
        if (t < o) red[t] += red[t + o];
        __syncthreads();
    }
    if (t == 0) out[b] = red[0] + pb[0];
}

// ------------------------------------------------------------------------------
extern "C" void kernel_launch(void* const* d_in, const int* in_sizes, int n_in,
                              void* d_out, int out_size) {
    const int*   atoms      = (const int*)  d_in[0];
    const float* atoms_mask = (const float*)d_in[1];
    const int*   adjacency  = (const int*)  d_in[2];
    const int*   amino      = (const int*)  d_in[3];
    const float* amino_mask = (const float*)d_in[4];
    const float* E_atom     = (const float*)d_in[5];
    const float* E_amino    = (const float*)d_in[6];
    const float* W_gat      = (const float*)d_in[7];
    const float* a_gat      = (const float*)d_in[8];
    const float* W_go       = (const float*)d_in[9];
    const float* a_go       = (const float*)d_in[10];
    const float* W_comp_w   = (const float*)d_in[11];
    const float* W_comp_b   = (const float*)d_in[12];
    const float* conv_w     = (const float*)d_in[13];
    const float* conv_b     = (const float*)d_in[14];
    const float* W_att_w    = (const float*)d_in[15];
    const float* W_att_b    = (const float*)d_in[16];
    const float* pred_w     = (const float*)d_in[17];
    const float* pred_b     = (const float*)d_in[18];
    float* outp = (float*)d_out;

    float *p_Wh, *p_src, *p_dst, *p_multi, *p_Wh2, *p_src2, *p_dst2;
    float *p_x, *p_atoms_vec, *p_pv0, *p_pv1, *p_part, *p_part2;
    cudaGetSymbolAddress((void**)&p_Wh, g_Wh);
    cudaGetSymbolAddress((void**)&p_src, g_src);
    cudaGetSymbolAddress((void**)&p_dst, g_dst);
    cudaGetSymbolAddress((void**)&p_multi, g_multi);
    cudaGetSymbolAddress((void**)&p_Wh2, g_Wh2);
    cudaGetSymbolAddress((void**)&p_src2, g_src2);
    cudaGetSymbolAddress((void**)&p_dst2, g_dst2);
    cudaGetSymbolAddress((void**)&p_x, g_x);
    cudaGetSymbolAddress((void**)&p_atoms_vec, g_atoms_vec);
    cudaGetSymbolAddress((void**)&p_pv0, g_pv0);
    cudaGetSymbolAddress((void**)&p_pv1, g_pv1);
    cudaGetSymbolAddress((void**)&p_part, g_part);
    cudaGetSymbolAddress((void**)&p_part2, g_part2);

    // fork stream + events for the independent protein path (capture-legal;
    // never destroyed — destroying mid-capture invalidates the graph).
    cudaStream_t s2;
    cudaEvent_t evFork, evJoin;
    cudaStreamCreateWithFlags(&s2, cudaStreamNonBlocking);
    cudaEventCreateWithFlags(&evFork, cudaEventDisableTiming);
    cudaEventCreateWithFlags(&evJoin, cudaEventDisableTiming);

    // zero accumulators (graph-capturable memset nodes)
    cudaMemsetAsync(p_part,  0, B_*LT*sizeof(float));
    cudaMemsetAsync(p_part2, 0, B_*LT*sizeof(float));
    cudaMemsetAsync(p_src,  0, NH*B_*NA*sizeof(float));
    cudaMemsetAsync(p_dst,  0, NH*B_*NA*sizeof(float));
    cudaMemsetAsync(p_src2, 0, B_*NA*sizeof(float));
    cudaMemsetAsync(p_dst2, 0, B_*NA*sizeof(float));

    // -------- fork: protein path on s2 --------
    cudaEventRecord(evFork, 0);
    cudaStreamWaitEvent(s2, evFork, 0);
    conv11r<true ><<<dim3(4,32,B_), 256, 0, s2>>>(E_amino, amino, conv_w, conv_b, 0, p_pv1);
    conv11r<false><<<dim3(4,32,B_), 256, 0, s2>>>(p_pv1, amino, conv_w, conv_b, 1, p_pv0);
    conv11r<false><<<dim3(4,32,B_), 256, 0, s2>>>(p_pv0, amino, conv_w, conv_b, 2, p_pv1);
    sgemmX<true,2,false,false><<<dim3(2,8,B_), 256, 0, s2>>>(
        p_pv1, W_att_w, W_att_b, nullptr, nullptr, nullptr, nullptr, nullptr,
        amino_mask, p_part2,
        LA, LT, LT, (size_t)LA*LT, 0, 0, 1, 0);
    cudaEventRecord(evJoin, s2);

    // -------- atom/GAT path on default stream --------
    // 1. layer-1 GAT projection (gather + fused src/dst dots; head = z/B_)
    sgemmX<false,0,true,true><<<dim3(1,4,NH*B_), 256>>>(
        E_atom, W_gat, nullptr, p_Wh, atoms, a_gat, p_src, p_dst, nullptr, nullptr,
        NA, GD, CD, 0, B_, (size_t)CD*GD, B_, (size_t)NA*GD);
    attn64<GD><<<dim3(NA/64, NH*B_, 1), 256>>>(p_Wh, p_src, p_dst,
        adjacency, p_multi, NH*GD, B_);

    // 2. layer-2 GAT projection (fused src/dst dots; bDiv=B_ so avec head = 0)
    sgemmX<false,0,false,true><<<dim3(2,4,B_), 256>>>(
        p_multi, W_go, nullptr, p_Wh2, nullptr, a_go, p_src2, p_dst2, nullptr, nullptr,
        NA, CD, NH*GD, (size_t)NA*NH*GD, 0, 0, B_, (size_t)NA*CD);
    attn64<CD><<<dim3(NA/64, B_, 2), 256>>>(p_Wh2, p_src2, p_dst2,
        adjacency, p_x, CD, B_);

    // 3. atoms_vec = lrelu(x @ Wc^T + bc);  pool(lrelu(atoms_vec @ Wa^T + ba))
    sgemmX<true,1,false,false><<<dim3(2,4,B_), 256>>>(
        p_x, W_comp_w, W_comp_b, p_atoms_vec, nullptr, nullptr, nullptr, nullptr, nullptr, nullptr,
        NA, LT, CD, (size_t)NA*CD, 0, 0, 1, (size_t)NA*LT);
    sgemmX<true,2,false,false><<<dim3(2,4,B_), 256>>>(
        p_atoms_vec, W_att_w, W_att_b, nullptr, nullptr, nullptr, nullptr, nullptr,
        atoms_mask, p_part,
        NA, LT, LT, (size_t)NA*LT, 0, 0, 1, 0);

    // -------- join + finalize --------
    cudaStreamWaitEvent(0, evJoin, 0);
    finalize<<<B_, 256>>>(p_part, p_part2, atoms_mask, amino_mask, pred_w, pred_b, outp);
}

// round 13
// speedup vs baseline: 2.5071x; 1.0656x over previous
#include <cuda_runtime.h>
#include <math.h>

#define B_  16
#define NA  512
#define LA  1024
#define CD  128
#define GD  64
#define NH  4
#define LT  128
#define ALPHA 0.2f

typedef unsigned long long u64;

static __device__ __forceinline__ u64 fma2(u64 a, u64 b, u64 c) {
    u64 d;
    asm("fma.rn.f32x2 %0, %1, %2, %3;" : "=l"(d) : "l"(a), "l"(b), "l"(c));
    return d;
}
static __device__ __forceinline__ u64 pack2(float lo, float hi) {
    u64 r;
    asm("mov.b64 %0, {%1, %2};" : "=l"(r) : "f"(lo), "f"(hi));
    return r;
}
static __device__ __forceinline__ float2 u2f(u64 v) {
    float2 r;
    asm("mov.b64 {%0, %1}, %2;" : "=f"(r.x), "=f"(r.y) : "l"(v));
    return r;
}
static __device__ __forceinline__ void cp16(unsigned s, const void* g) {
    asm volatile("cp.async.cg.shared.global [%0], [%1], 16;" :: "r"(s), "l"(g));
}
static __device__ __forceinline__ void cp_commit() {
    asm volatile("cp.async.commit_group;");
}
template<int N> static __device__ __forceinline__ void cp_wait() {
    asm volatile("cp.async.wait_group %0;" :: "n"(N));
}

// ---------------- scratch (static device globals; no allocations) -------------
__device__ float g_Wh[NH*B_*NA*GD];
__device__ float g_src[NH*B_*NA];
__device__ float g_dst[NH*B_*NA];
__device__ float g_multi[B_*NA*NH*GD];
__device__ float g_Wh2[B_*NA*CD];
__device__ float g_src2[B_*NA];
__device__ float g_dst2[B_*NA];
__device__ float g_x[B_*NA*CD];
__device__ float g_atoms_vec[B_*NA*LT];
__device__ float g_pv0[B_*LA*CD];
__device__ float g_pv1[B_*LA*CD];
__device__ float g_part[B_*LT];
__device__ float g_part2[B_*LT];

// ---------------- SGEMM, f32x2, cp.async double-buffered ----------------------
// BM=128 BN=64 BK=16, 256 threads, 8x4 microtile; column map n = tx + 16*j.
template<bool BT, int EPI, bool GATHER, bool SRCDST>
__global__ __launch_bounds__(256, 2) void sgemmX(
        const float* __restrict__ A, const float* __restrict__ Bm,
        const float* __restrict__ bias, float* __restrict__ C,
        const int* __restrict__ gidx,
        const float* __restrict__ avec, float* __restrict__ srcO, float* __restrict__ dstO,
        const float* __restrict__ mask, float* __restrict__ part,
        int M, int N, int K,
        size_t aBat, int aMod, size_t bBat, int bDiv, size_t cBat) {
    __shared__ __align__(16) float As_t[2][128*16];
    __shared__ __align__(16) float Bs_t[2][64*20];
    int z = blockIdx.z;
    int zb = aMod ? (z % aMod) : z;
    if (!GATHER) A += (size_t)zb * aBat;
    Bm += (size_t)(bDiv ? (z / bDiv) : z) * bBat;
    C  += (size_t)z * cBat;
    int bn = blockIdx.x * 64, bm = blockIdx.y * 128;
    int tid = threadIdx.x;
    int tx = tid & 15, ty = tid >> 4;
    unsigned asBase = (unsigned)__cvta_generic_to_shared(&As_t[0][0]);
    unsigned bsBase = (unsigned)__cvta_generic_to_shared(&Bs_t[0][0]);

    // staging indices
    int am0 = tid >> 2, ak0 = (tid & 3) * 4;            // A: 2 passes
    int btn = tid >> 2, btk = (tid & 3) * 4;            // B (BT)
    int bfk = tid >> 4, bfn = (tid & 15) * 4;           // B (!BT)

    #define STAGE_A(k0, bf) do {                                               \
        int m0 = am0, m1 = am0 + 64;                                           \
        const float *sp0, *sp1;                                                \
        if (GATHER) {                                                          \
            sp0 = &A[(size_t)gidx[(size_t)zb*M + bm + m0]*K + (k0) + ak0];     \
            sp1 = &A[(size_t)gidx[(size_t)zb*M + bm + m1]*K + (k0) + ak0];     \
        } else {                                                               \
            sp0 = &A[(size_t)(bm + m0)*K + (k0) + ak0];                        \
            sp1 = &A[(size_t)(bm + m1)*K + (k0) + ak0];                        \
        }                                                                      \
        cp16(asBase + ((bf)*2048 + m0*16 + ak0)*4, sp0);                       \
        cp16(asBase + ((bf)*2048 + m1*16 + ak0)*4, sp1);                       \
    } while (0)
    #define STAGE_BT(k0, bf) \
        cp16(bsBase + ((bf)*1280 + btn*20 + btk)*4, &Bm[(size_t)(bn + btn)*K + (k0) + btk])

    // ---- prologue: stage chunk 0 ----
    STAGE_A(0, 0);
    if (BT) STAGE_BT(0, 0);
    cp_commit();
    if (!BT) {
        float4 v = *(const float4*)&Bm[(size_t)bfk * N + bn + bfn];
        Bs_t[0][(bfn+0)*20 + bfk] = v.x;
        Bs_t[0][(bfn+1)*20 + bfk] = v.y;
        Bs_t[0][(bfn+2)*20 + bfk] = v.z;
        Bs_t[0][(bfn+3)*20 + bfk] = v.w;
    }
    cp_wait<0>();
    __syncthreads();

    u64 acc[8][4] = {};
    int buf = 0;
    for (int k0 = 0; k0 < K; k0 += 16) {
        int nxt = k0 + 16;
        bool has = nxt < K;
        float4 bstage;
        if (has) {
            STAGE_A(nxt, buf ^ 1);
            if (BT) STAGE_BT(nxt, buf ^ 1);
            cp_commit();
            if (!BT) bstage = *(const float4*)&Bm[(size_t)(nxt + bfk)*N + bn + bfn];
        }
        // ---- compute current chunk ----
        #pragma unroll
        for (int q = 0; q < 4; q++) {
            ulonglong2 aQ[8];
            #pragma unroll
            for (int i = 0; i < 8; i++)
                aQ[i] = *(const ulonglong2*)&As_t[buf][(ty*8 + i)*16 + q*4];
            #pragma unroll
            for (int j = 0; j < 4; j++) {
                ulonglong2 bq = *(const ulonglong2*)&Bs_t[buf][(tx + 16*j)*20 + q*4];
                #pragma unroll
                for (int i = 0; i < 8; i++) {
                    acc[i][j] = fma2(aQ[i].x, bq.x, acc[i][j]);
                    acc[i][j] = fma2(aQ[i].y, bq.y, acc[i][j]);
                }
            }
        }
        if (has) {
            if (!BT) {
                Bs_t[buf^1][(bfn+0)*20 + bfk] = bstage.x;
                Bs_t[buf^1][(bfn+1)*20 + bfk] = bstage.y;
                Bs_t[buf^1][(bfn+2)*20 + bfk] = bstage.z;
                Bs_t[buf^1][(bfn+3)*20 + bfk] = bstage.w;
            }
            cp_wait<0>();
            __syncthreads();
            buf ^= 1;
        }
    }
    #undef STAGE_A
    #undef STAGE_BT

    float vv[8][4];
    #pragma unroll
    for (int i = 0; i < 8; i++)
        #pragma unroll
        for (int j = 0; j < 4; j++) {
            float2 p = u2f(acc[i][j]);
            float v = p.x + p.y;
            if (EPI >= 1) {
                v += bias[bn + tx + 16*j];
                v = (v >= 0.f) ? v : ALPHA * v;
            }
            vv[i][j] = v;
        }
    if (EPI == 2) {
        const float* maskB = mask + (size_t)z * M;
        float cs[4] = {};
        #pragma unroll
        for (int i = 0; i < 8; i++) {
            float mk = maskB[bm + ty*8 + i];
            #pragma unroll
            for (int j = 0; j < 4; j++) cs[j] += vv[i][j] * mk;
        }
        __syncthreads();
        float* sred = &As_t[0][0];  // reuse: [16][64]
        #pragma unroll
        for (int j = 0; j < 4; j++) sred[ty*64 + tx + 16*j] = cs[j];
        __syncthreads();
        if (tid < 64) {
            float s = 0.f;
            #pragma unroll
            for (int t = 0; t < 16; t++) s += sred[t*64 + tid];
            atomicAdd(&part[(size_t)z * LT + bn + tid], s);
        }
        return;
    }
    #pragma unroll
    for (int i = 0; i < 8; i++) {
        int m = bm + ty*8 + i;
        #pragma unroll
        for (int j = 0; j < 4; j++)
            C[(size_t)m * N + bn + tx + 16*j] = vv[i][j];
    }
    if (SRCDST) {
        const float* av = avec + (size_t)(bDiv ? (z / bDiv) : 0) * 2 * N;
        float a0[4], a1[4];
        #pragma unroll
        for (int j = 0; j < 4; j++) {
            a0[j] = av[bn + tx + 16*j];
            a1[j] = av[N + bn + tx + 16*j];
        }
        #pragma unroll
        for (int i = 0; i < 8; i++) {
            float s = 0.f, d = 0.f;
            #pragma unroll
            for (int j = 0; j < 4; j++) {
                s += vv[i][j] * a0[j];
                d += vv[i][j] * a1[j];
            }
            #pragma unroll
            for (int o = 8; o; o >>= 1) {
                s += __shfl_xor_sync(0xffffffffu, s, o);
                d += __shfl_xor_sync(0xffffffffu, d, o);
            }
            if (tx == 0) {
                int m = bm + ty*8 + i;
                atomicAdd(&srcO[(size_t)z * M + m], s);
                atomicAdd(&dstO[(size_t)z * M + m], d);
            }
        }
    }
}

// ---------------- fused GAT attention: 64-row tiles, cp.async pipeline --------
// grid: (NA/64, nb*heads, F/64). 256 threads = 8 warps x 8 rows. Wh chunks
// staged RAW (no transpose) double-buffered via cp.async; jj-pairs packed at
// compute time (conflict-free LDS.32). rowsumS aliases whs after the loop.
// Chunk = 64 rows x 64 cols of floats = 1024 cp16 copies: e = tid + p*256,
// row = e>>4 (0..63), col = (e&15)*4.
template<int F>
__global__ __launch_bounds__(256, 2) void attn64(
        const float* __restrict__ Wh, const float* __restrict__ src,
        const float* __restrict__ dst, const int* __restrict__ adj,
        float* __restrict__ out, int outRowStride, int nb) {
    __shared__ __align__(16) float wsm[64*64];       // 16 KB
    __shared__ __align__(16) float whs[2][64*64];    // 32 KB
    int hb = blockIdx.y;
    int b = hb % nb, h = hb / nb;
    int half = blockIdx.z;
    const float* WhB  = Wh  + (size_t)hb * NA * F + half*64;
    const float* srcB = src + (size_t)hb * NA;
    const float* dstB = dst + (size_t)hb * NA;
    const int*   adjB = adj + (size_t)b * NA * NA;
    int row0 = blockIdx.x * 64;
    int tid = threadIdx.x;
    int ra = tid >> 2, ga = tid & 3;
    float srow = srcB[row0 + ra];
    const int* arow = adjB + (size_t)(row0 + ra) * NA + ga * 16;
    int tx = tid & 31, ty = tid >> 5;
    unsigned whsBase = (unsigned)__cvta_generic_to_shared(&whs[0][0]);
    int sr = tid >> 4, sc = (tid & 15) * 4;   // staging: 4 passes, row += 16

    u64 acc[8][2] = {};
    float psum = 0.f;

    // prologue: stage chunk 0
    #pragma unroll
    for (int p = 0; p < 4; p++) {
        int r = sr + p*16;
        cp16(whsBase + (0*4096 + r*64 + sc)*4, WhB + (size_t)r * F + sc);
    }
    cp_commit();

    int buf = 0;
    for (int jc = 0; jc < NA; jc += 64) {
        // ---- phase A: masked exp(leaky(src+dst)) -> wsm[64][64] ----
        const int4* ap = (const int4*)(arow + jc);
        const float4* dp = (const float4*)(dstB + jc + ga*16);
        #pragma unroll
        for (int v = 0; v < 4; v++) {
            int4 a4 = ap[v];
            float4 d4 = dp[v];
            int   am[4] = {a4.x, a4.y, a4.z, a4.w};
            float dv[4] = {d4.x, d4.y, d4.z, d4.w};
            float w[4];
            #pragma unroll
            for (int k = 0; k < 4; k++) {
                float t = srow + dv[k];
                t = (t >= 0.f) ? t : ALPHA * t;
                float ex = (am[k] > 0) ? __expf(t) : 0.f;
                w[k] = ex;
                psum += ex;
            }
            *(float4*)&wsm[ra*64 + ga*16 + v*4] = make_float4(w[0], w[1], w[2], w[3]);
        }
        // ---- stage next chunk (raw) into buf^1 ----
        bool has = (jc + 64) < NA;
        if (has) {
            const float* nsrc = WhB + (size_t)(jc + 64) * F;
            #pragma unroll
            for (int p = 0; p < 4; p++) {
                int r = sr + p*16;
                cp16(whsBase + ((buf^1)*4096 + r*64 + sc)*4, nsrc + (size_t)r * F + sc);
            }
            cp_commit();
            cp_wait<1>();
        } else {
            cp_wait<0>();
        }
        __syncthreads();
        // ---- acc += w[64][64] @ WhT, jj-pairs packed from raw rows ----
        #pragma unroll
        for (int jb = 0; jb < 16; jb++) {
            ulonglong2 wr[8];
            #pragma unroll
            for (int t = 0; t < 8; t++)
                wr[t] = *(const ulonglong2*)&wsm[(ty*8 + t)*64 + jb*4];
            #pragma unroll
            for (int q = 0; q < 2; q++) {
                int jj = jb*4 + q*2;
                #pragma unroll
                for (int u = 0; u < 2; u++) {
                    int n = tx + 32*u;
                    u64 wv = pack2(whs[buf][jj*64 + n], whs[buf][(jj+1)*64 + n]);
                    #pragma unroll
                    for (int t = 0; t < 8; t++)
                        acc[t][u] = fma2(q == 0 ? wr[t].x : wr[t].y, wv, acc[t][u]);
                }
            }
        }
        __syncthreads();
        buf ^= 1;
    }
    // row sums (4 threads per row); rowsumS aliases whs (all reads done)
    float* rowsumS = &whs[0][0];
    #pragma unroll
    for (int o = 2; o; o >>= 1) psum += __shfl_down_sync(0xffffffffu, psum, o, 4);
    if (ga == 0) rowsumS[ra] = psum;
    __syncthreads();
    // normalize + elu + store
    int colOff = h * F + half * 64;
    #pragma unroll
    for (int t = 0; t < 8; t++) {
        int r = ty*8 + t;
        float inv = 1.f / rowsumS[r];
        float* op = out + ((size_t)b * NA + row0 + r) * outRowStride + colOff;
        #pragma unroll
        for (int u = 0; u < 2; u++) {
            float2 pr = u2f(acc[t][u]);
            float v = (pr.x + pr.y) * inv;
            v = (v > 0.f) ? v : expm1f(v);
            op[tx + 32*u] = v;
        }
    }
}

// ---------------- 11x11 conv, SAME pad, relu, 4 outputs/thread ----------------
template<bool G>
__global__ __launch_bounds__(256) void conv11r(const float* __restrict__ in,
        const int* __restrict__ gidx, const float* __restrict__ wconv,
        const float* __restrict__ bconv, int layer, float* __restrict__ out) {
    __shared__ float tile[42][42];
    __shared__ float ws[121];
    int b = blockIdx.z, ly0 = blockIdx.y * 32, lx0 = blockIdx.x * 32;
    int tid = threadIdx.x;
    int tx = tid & 31, ty = tid >> 5;
    if (tid < 121) ws[tid] = wconv[layer*121 + tid];
    const float* inb = in + (size_t)b * LA * CD;
    const int* gb = gidx + (size_t)b * LA;
    for (int e = tid; e < 42*42; e += 256) {
        int sy = e / 42, sx = e % 42;
        int gy = ly0 + sy - 5, gx = lx0 + sx - 5;
        float val = 0.f;
        if (gy >= 0 && gy < LA && gx >= 0 && gx < CD) {
            if (G) val = in[(size_t)gb[gy]*CD + gx];
            else   val = inb[(size_t)gy*CD + gx];
        }
        tile[sy][sx] = val;
    }
    __syncthreads();
    float bz = bconv[layer];
    float acc[4] = {bz, bz, bz, bz};
    #pragma unroll
    for (int kx = 0; kx < 11; kx++) {
        float v[14];
        #pragma unroll
        for (int r = 0; r < 14; r++) v[r] = tile[ty*4 + r][tx + kx];
        #pragma unroll
        for (int ky = 0; ky < 11; ky++) {
            float wv = ws[ky*11 + kx];
            #pragma unroll
            for (int i = 0; i < 4; i++) acc[i] += v[ky + i] * wv;
        }
    }
    #pragma unroll
    for (int i = 0; i < 4; i++)
        out[(size_t)b*LA*CD + (size_t)(ly0 + ty*4 + i)*CD + lx0 + tx] = fmaxf(acc[i], 0.f);
}

// ---------------- finalize: pools -> lrelu^2 -> dot ---------------------------
__global__ void finalize(const float* __restrict__ part, const float* __restrict__ part2,
                         const float* __restrict__ amask, const float* __restrict__ pmask,
                         const float* __restrict__ pw, const float* __restrict__ pb,
                         float* __restrict__ out) {
    __shared__ float redA[256], redB[256], red[256];
    int b = blockIdx.x, t = threadIdx.x;
    float msA = 0.f, msP = 0.f;
    for (int i = t; i < NA; i += 256) msA += amask[(size_t)b*NA + i];
    for (int i = t; i < LA; i += 256) msP += pmask[(size_t)b*LA + i];
    redA[t] = msA; redB[t] = msP;
    __syncthreads();
    for (int o = 128; o; o >>= 1) {
        if (t < o) { redA[t] += redA[t+o]; redB[t] += redB[t+o]; }
        __syncthreads();
    }
    float v = (t < 128) ? part[b*LT + t] / redA[0] : part2[b*LT + (t - 128)] / redB[0];
    v = (v >= 0.f) ? v : ALPHA * v;
    v = (v >= 0.f) ? v : ALPHA * v;
    red[t] = v * pw[t];
    __syncthreads();
    for (int o = 128; o; o >>= 1) {
        if (t < o) red[t] += red[t + o];
        __syncthreads();
    }
    if (t == 0) out[b] = red[0] + pb[0];
}

// ------------------------------------------------------------------------------
extern "C" void kernel_launch(void* const* d_in, const int* in_sizes, int n_in,
                              void* d_out, int out_size) {
    const int*   atoms      = (const int*)  d_in[0];
    const float* atoms_mask = (const float*)d_in[1];
    const int*   adjacency  = (const int*)  d_in[2];
    const int*   amino      = (const int*)  d_in[3];
    const float* amino_mask = (const float*)d_in[4];
    const float* E_atom     = (const float*)d_in[5];
    const float* E_amino    = (const float*)d_in[6];
    const float* W_gat      = (const float*)d_in[7];
    const float* a_gat      = (const float*)d_in[8];
    const float* W_go       = (const float*)d_in[9];
    const float* a_go       = (const float*)d_in[10];
    const float* W_comp_w   = (const float*)d_in[11];
    const float* W_comp_b   = (const float*)d_in[12];
    const float* conv_w     = (const float*)d_in[13];
    const float* conv_b     = (const float*)d_in[14];
    const float* W_att_w    = (const float*)d_in[15];
    const float* W_att_b    = (const float*)d_in[16];
    const float* pred_w     = (const float*)d_in[17];
    const float* pred_b     = (const float*)d_in[18];
    float* outp = (float*)d_out;

    float *p_Wh, *p_src, *p_dst, *p_multi, *p_Wh2, *p_src2, *p_dst2;
    float *p_x, *p_atoms_vec, *p_pv0, *p_pv1, *p_part, *p_part2;
    cudaGetSymbolAddress((void**)&p_Wh, g_Wh);
    cudaGetSymbolAddress((void**)&p_src, g_src);
    cudaGetSymbolAddress((void**)&p_dst, g_dst);
    cudaGetSymbolAddress((void**)&p_multi, g_multi);
    cudaGetSymbolAddress((void**)&p_Wh2, g_Wh2);
    cudaGetSymbolAddress((void**)&p_src2, g_src2);
    cudaGetSymbolAddress((void**)&p_dst2, g_dst2);
    cudaGetSymbolAddress((void**)&p_x, g_x);
    cudaGetSymbolAddress((void**)&p_atoms_vec, g_atoms_vec);
    cudaGetSymbolAddress((void**)&p_pv0, g_pv0);
    cudaGetSymbolAddress((void**)&p_pv1, g_pv1);
    cudaGetSymbolAddress((void**)&p_part, g_part);
    cudaGetSymbolAddress((void**)&p_part2, g_part2);

    // fork stream + events for the independent protein path (capture-legal;
    // never destroyed — destroying mid-capture invalidates the graph).
    cudaStream_t s2;
    cudaEvent_t evFork, evJoin;
    cudaStreamCreateWithFlags(&s2, cudaStreamNonBlocking);
    cudaEventCreateWithFlags(&evFork, cudaEventDisableTiming);
    cudaEventCreateWithFlags(&evJoin, cudaEventDisableTiming);

    // zero accumulators (graph-capturable memset nodes)
    cudaMemsetAsync(p_part,  0, B_*LT*sizeof(float));
    cudaMemsetAsync(p_part2, 0, B_*LT*sizeof(float));
    cudaMemsetAsync(p_src,  0, NH*B_*NA*sizeof(float));
    cudaMemsetAsync(p_dst,  0, NH*B_*NA*sizeof(float));
    cudaMemsetAsync(p_src2, 0, B_*NA*sizeof(float));
    cudaMemsetAsync(p_dst2, 0, B_*NA*sizeof(float));

    // -------- fork: protein path on s2 --------
    cudaEventRecord(evFork, 0);
    cudaStreamWaitEvent(s2, evFork, 0);
    conv11r<true ><<<dim3(4,32,B_), 256, 0, s2>>>(E_amino, amino, conv_w, conv_b, 0, p_pv1);
    conv11r<false><<<dim3(4,32,B_), 256, 0, s2>>>(p_pv1, amino, conv_w, conv_b, 1, p_pv0);
    conv11r<false><<<dim3(4,32,B_), 256, 0, s2>>>(p_pv0, amino, conv_w, conv_b, 2, p_pv1);
    sgemmX<true,2,false,false><<<dim3(2,8,B_), 256, 0, s2>>>(
        p_pv1, W_att_w, W_att_b, nullptr, nullptr, nullptr, nullptr, nullptr,
        amino_mask, p_part2,
        LA, LT, LT, (size_t)LA*LT, 0, 0, 1, 0);
    cudaEventRecord(evJoin, s2);

    // -------- atom/GAT path on default stream --------
    // 1. layer-1 GAT projection (gather + fused src/dst dots; head = z/B_)
    sgemmX<false,0,true,true><<<dim3(1,4,NH*B_), 256>>>(
        E_atom, W_gat, nullptr, p_Wh, atoms, a_gat, p_src, p_dst, nullptr, nullptr,
        NA, GD, CD, 0, B_, (size_t)CD*GD, B_, (size_t)NA*GD);
    attn64<GD><<<dim3(NA/64, NH*B_, 1), 256>>>(p_Wh, p_src, p_dst,
        adjacency, p_multi, NH*GD, B_);

    // 2. layer-2 GAT projection (fused src/dst dots; bDiv=B_ so avec head = 0)
    sgemmX<false,0,false,true><<<dim3(2,4,B_), 256>>>(
        p_multi, W_go, nullptr, p_Wh2, nullptr, a_go, p_src2, p_dst2, nullptr, nullptr,
        NA, CD, NH*GD, (size_t)NA*NH*GD, 0, 0, B_, (size_t)NA*CD);
    attn64<CD><<<dim3(NA/64, B_, 2), 256>>>(p_Wh2, p_src2, p_dst2,
        adjacency, p_x, CD, B_);

    // 3. atoms_vec = lrelu(x @ Wc^T + bc);  pool(lrelu(atoms_vec @ Wa^T + ba))
    sgemmX<true,1,false,false><<<dim3(2,4,B_), 256>>>(
        p_x, W_comp_w, W_comp_b, p_atoms_vec, nullptr, nullptr, nullptr, nullptr, nullptr, nullptr,
        NA, LT, CD, (size_t)NA*CD, 0, 0, 1, (size_t)NA*LT);
    sgemmX<true,2,false,false><<<dim3(2,4,B_), 256>>>(
        p_atoms_vec, W_att_w, W_att_b, nullptr, nullptr, nullptr, nullptr, nullptr,
        atoms_mask, p_part,
        NA, LT, LT, (size_t)NA*LT, 0, 0, 1, 0);

    // -------- join + finalize --------
    cudaStreamWaitEvent(0, evJoin, 0);
    finalize<<<B_, 256>>>(p_part, p_part2, atoms_mask, amino_mask, pred_w, pred_b, outp);
}